// round 1
// baseline (speedup 1.0000x reference)
#include <cuda_runtime.h>
#include <cuda_bf16.h>
#include <cstdint>

// Problem constants
#define B_   8
#define S_   1024
#define D_   1024
#define H_   16
#define HD_  64
#define ROWS (B_ * S_)          // 8192
#define EPS_ 1e-5f

// ---------------- scratch (device globals, no allocation) ----------------
__device__ float    g_Xq[ROWS * D_];      // fc_q(lif(Q))
__device__ float    g_Xk[ROWS * D_];      // fc_k(lif(K))
__device__ float    g_V [ROWS * D_];      // fc_v(lif(K))
__device__ float    g_At[ROWS * D_];      // attention output (pre-Wo)
__device__ unsigned g_qb[ROWS * 32];      // q bits: [row][32 words], word = dims d/32
__device__ unsigned g_kb[ROWS * 32];      // k bits

// ---------------- helpers ----------------
__device__ __forceinline__ float mishf(float x) {
    float sp = (x > 20.f) ? x : log1pf(__expf(x));
    return x * tanhf(sp);
}

// ---------------- SGEMM: C[M,N] = op(A)[M,K] @ W[N,K]^T + bias ----------------
// BIN:  binarize A on load (x >= 2 ? 1 : 0)
// MISH: epilogue out = A[m][n] + mish(c)   (requires K == N)
template<bool BIN, bool MISH>
__global__ __launch_bounds__(256)
void sgemm(const float* __restrict__ A, const float* __restrict__ W,
           const float* __restrict__ bias, float* __restrict__ C,
           int M, int N, int K)
{
    __shared__ float As[16][128];
    __shared__ float Bs[16][128];

    const int tid = threadIdx.x;
    const int bn  = blockIdx.x * 128;
    const int bm  = blockIdx.y * 128;
    const int tx  = tid & 15;
    const int ty  = tid >> 4;

    float acc[8][8];
#pragma unroll
    for (int i = 0; i < 8; i++)
#pragma unroll
        for (int j = 0; j < 8; j++) acc[i][j] = 0.f;

    const float* Ag = A + (size_t)bm * K;
    const float* Wg = W + (size_t)bn * K;

    for (int k0 = 0; k0 < K; k0 += 16) {
#pragma unroll
        for (int i = 0; i < 2; i++) {
            int id  = tid + 256 * i;     // 0..511
            int row = id >> 2;           // 0..127
            int c4  = (id & 3) * 4;      // 0,4,8,12
            float4 a4 = *(const float4*)(Ag + (size_t)row * K + k0 + c4);
            if (BIN) {
                a4.x = a4.x >= 2.f ? 1.f : 0.f;
                a4.y = a4.y >= 2.f ? 1.f : 0.f;
                a4.z = a4.z >= 2.f ? 1.f : 0.f;
                a4.w = a4.w >= 2.f ? 1.f : 0.f;
            }
            As[c4 + 0][row] = a4.x; As[c4 + 1][row] = a4.y;
            As[c4 + 2][row] = a4.z; As[c4 + 3][row] = a4.w;
            float4 b4 = *(const float4*)(Wg + (size_t)row * K + k0 + c4);
            Bs[c4 + 0][row] = b4.x; Bs[c4 + 1][row] = b4.y;
            Bs[c4 + 2][row] = b4.z; Bs[c4 + 3][row] = b4.w;
        }
        __syncthreads();
#pragma unroll
        for (int kk = 0; kk < 16; kk++) {
            float a[8], b[8];
#pragma unroll
            for (int i = 0; i < 8; i++) a[i] = As[kk][ty * 8 + i];
#pragma unroll
            for (int j = 0; j < 8; j++) b[j] = Bs[kk][tx * 8 + j];
#pragma unroll
            for (int i = 0; i < 8; i++)
#pragma unroll
                for (int j = 0; j < 8; j++)
                    acc[i][j] += a[i] * b[j];
        }
        __syncthreads();
    }

#pragma unroll
    for (int i = 0; i < 8; i++) {
        int m = bm + ty * 8 + i;
#pragma unroll
        for (int j = 0; j < 8; j += 4) {
            int n = bn + tx * 8 + j;
            float4 r;
            r.x = acc[i][j + 0] + bias[n + 0];
            r.y = acc[i][j + 1] + bias[n + 1];
            r.z = acc[i][j + 2] + bias[n + 2];
            r.w = acc[i][j + 3] + bias[n + 3];
            if (MISH) {
                float4 av = *(const float4*)(A + (size_t)m * K + n); // K == N
                r.x = av.x + mishf(r.x);
                r.y = av.y + mishf(r.y);
                r.z = av.z + mishf(r.z);
                r.w = av.w + mishf(r.w);
            }
            *(float4*)(C + (size_t)m * N + n) = r;
        }
    }
}

// ---------------- LayerNorm + LIF + bit-pack ----------------
// One block per row of 1024. y = (x-mu)*rsqrt(var+eps)*g + b ; bit = (y >= 2)
__global__ __launch_bounds__(256)
void ln_lif_pack(const float* __restrict__ X,
                 const float* __restrict__ gamma, const float* __restrict__ beta,
                 unsigned* __restrict__ bits)
{
    const int row  = blockIdx.x;
    const int t    = threadIdx.x;
    const int lane = t & 31;
    const int wid  = t >> 5;

    const float* xr = X + (size_t)row * D_;

    float x[4];
    float s = 0.f, sq = 0.f;
#pragma unroll
    for (int i = 0; i < 4; i++) {
        x[i] = xr[i * 256 + t];
        s  += x[i];
        sq += x[i] * x[i];
    }
#pragma unroll
    for (int off = 16; off > 0; off >>= 1) {
        s  += __shfl_xor_sync(0xffffffffu, s,  off);
        sq += __shfl_xor_sync(0xffffffffu, sq, off);
    }
    __shared__ float ss[8], sqq[8];
    __shared__ float s_mu, s_rs;
    if (lane == 0) { ss[wid] = s; sqq[wid] = sq; }
    __syncthreads();
    if (wid == 0) {
        float a = (lane < 8) ? ss[lane]  : 0.f;
        float b = (lane < 8) ? sqq[lane] : 0.f;
#pragma unroll
        for (int off = 4; off > 0; off >>= 1) {
            a += __shfl_xor_sync(0xffffffffu, a, off);
            b += __shfl_xor_sync(0xffffffffu, b, off);
        }
        if (lane == 0) {
            float mu  = a * (1.f / D_);
            float var = b * (1.f / D_) - mu * mu;
            s_mu = mu;
            s_rs = rsqrtf(var + EPS_);
        }
    }
    __syncthreads();
    const float mu = s_mu, rs = s_rs;

#pragma unroll
    for (int i = 0; i < 4; i++) {
        int d = i * 256 + t;
        float y = (x[i] - mu) * rs * gamma[d] + beta[d];
        unsigned word = __ballot_sync(0xffffffffu, y >= 2.0f);
        if (lane == 0) bits[(size_t)row * 32 + i * 8 + wid] = word;
    }
}

// ---------------- flash attention with popcount QK ----------------
// grid (8 qblocks, 16 heads, 8 batch), 128 threads; each thread owns one q row.
__global__ __launch_bounds__(128)
void attn_kernel(const unsigned* __restrict__ qbits, const unsigned* __restrict__ kbits,
                 const float* __restrict__ V, const float* __restrict__ mask,
                 float* __restrict__ out)
{
    const int qblk = blockIdx.x;
    const int h    = blockIdx.y;
    const int b    = blockIdx.z;
    const int t    = threadIdx.x;
    const int qr   = qblk * 128 + t;

    __shared__ float    sV[32][64];
    __shared__ float    sM[128][33];
    __shared__ unsigned sKb[32][2];

    const unsigned q0 = qbits[((size_t)(b * S_ + qr)) * 32 + h * 2 + 0];
    const unsigned q1 = qbits[((size_t)(b * S_ + qr)) * 32 + h * 2 + 1];

    float4 acc[16];
#pragma unroll
    for (int i = 0; i < 16; i++) acc[i] = make_float4(0.f, 0.f, 0.f, 0.f);
    float ssum = 0.f;

    const float* maskB = mask + (size_t)b * S_ * S_;

    for (int k0 = 0; k0 < S_; k0 += 32) {
        if (t < 64) {
            int j = t >> 1, w = t & 1;
            sKb[j][w] = kbits[((size_t)(b * S_ + k0 + j)) * 32 + h * 2 + w];
        }
        const float4* Vg = (const float4*)(V + ((size_t)(b * S_ + k0)) * D_ + h * HD_);
#pragma unroll
        for (int i = 0; i < 4; i++) {
            int id = t + 128 * i;
            int j  = id >> 4, d4 = id & 15;
            ((float4*)&sV[j][0])[d4] = Vg[(size_t)j * 256 + d4];
        }
#pragma unroll
        for (int i = 0; i < 32; i++) {
            int r = i * 4 + (t >> 5);
            int c = t & 31;
            sM[r][c] = maskB[(size_t)(qblk * 128 + r) * S_ + k0 + c];
        }
        __syncthreads();
#pragma unroll
        for (int j = 0; j < 32; j++) {
            int sc = __popc(q0 & sKb[j][0]) + __popc(q1 & sKb[j][1]);
            float e = __expf((float)sc * 0.125f * sM[t][j]);
            ssum += e;
            const float4* vrow = (const float4*)&sV[j][0];
#pragma unroll
            for (int d = 0; d < 16; d++) {
                float4 v = vrow[d];
                acc[d].x += e * v.x;
                acc[d].y += e * v.y;
                acc[d].z += e * v.z;
                acc[d].w += e * v.w;
            }
        }
        __syncthreads();
    }
    const float inv = 1.f / ssum;
    float4* og = (float4*)(out + ((size_t)(b * S_ + qr)) * D_ + h * HD_);
#pragma unroll
    for (int d = 0; d < 16; d++) {
        float4 r = acc[d];
        r.x *= inv; r.y *= inv; r.z *= inv; r.w *= inv;
        og[d] = r;
    }
}

// ---------------- launch ----------------
extern "C" void kernel_launch(void* const* d_in, const int* in_sizes, int n_in,
                              void* d_out, int out_size)
{
    const float* Q   = (const float*)d_in[0];
    const float* K_  = (const float*)d_in[1];
    const float* adj = (const float*)d_in[2];
    const float* Wq  = (const float*)d_in[3];
    const float* bq  = (const float*)d_in[4];
    const float* Wk  = (const float*)d_in[5];
    const float* bk  = (const float*)d_in[6];
    const float* Wv  = (const float*)d_in[7];
    const float* bv  = (const float*)d_in[8];
    const float* Wo  = (const float*)d_in[9];
    const float* bo  = (const float*)d_in[10];
    const float* gq  = (const float*)d_in[11];
    const float* beq = (const float*)d_in[12];
    const float* gk  = (const float*)d_in[13];
    const float* bek = (const float*)d_in[14];
    float* out = (float*)d_out;

    float *Xq, *Xk, *Vb, *At;
    unsigned *qb, *kb;
    cudaGetSymbolAddress((void**)&Xq, g_Xq);
    cudaGetSymbolAddress((void**)&Xk, g_Xk);
    cudaGetSymbolAddress((void**)&Vb, g_V);
    cudaGetSymbolAddress((void**)&At, g_At);
    cudaGetSymbolAddress((void**)&qb, g_qb);
    cudaGetSymbolAddress((void**)&kb, g_kb);

    dim3 gg(D_ / 128, ROWS / 128);   // (8, 64)

    sgemm<true,  false><<<gg, 256>>>(Q,  Wq, bq, Xq, ROWS, D_, D_);
    sgemm<true,  false><<<gg, 256>>>(K_, Wk, bk, Xk, ROWS, D_, D_);
    sgemm<true,  false><<<gg, 256>>>(K_, Wv, bv, Vb, ROWS, D_, D_);

    ln_lif_pack<<<ROWS, 256>>>(Xq, gq, beq, qb);
    ln_lif_pack<<<ROWS, 256>>>(Xk, gk, bek, kb);

    attn_kernel<<<dim3(8, H_, B_), 128>>>(qb, kb, Vb, adj, At);

    sgemm<false, true><<<gg, 256>>>(At, Wo, bo, out, ROWS, D_, D_);
}

// round 2
// speedup vs baseline: 1.8976x; 1.8976x over previous
#include <cuda_runtime.h>
#include <cuda_bf16.h>
#include <cstdint>

// Problem constants
#define B_   8
#define S_   1024
#define D_   1024
#define H_   16
#define HD_  64
#define ROWS (B_ * S_)          // 8192
#define EPS_ 1e-5f

// GEMM tiling
#define BM 128
#define BN 128
#define BK 32
#define KP 40   // padded K stride (bf16 elems) -> conflict-free ldmatrix

// ---------------- scratch (device globals, no allocation) ----------------
__device__ float    g_Xq[ROWS * D_];
__device__ float    g_Xk[ROWS * D_];
__device__ float    g_V [ROWS * D_];
__device__ float    g_At[ROWS * D_];
__device__ unsigned g_qb[ROWS * 32];
__device__ unsigned g_kb[ROWS * 32];

// ---------------- helpers ----------------
__device__ __forceinline__ float mishf(float x) {
    float sp = (x > 20.f) ? x : log1pf(__expf(x));
    return x * tanhf(sp);
}

__device__ __forceinline__ unsigned pack2(__nv_bfloat16 a, __nv_bfloat16 b) {
    __nv_bfloat162 t = __halves2bfloat162(a, b);
    return *reinterpret_cast<unsigned*>(&t);
}

__device__ __forceinline__ void ldm4(unsigned* r, const __nv_bfloat16* p) {
    unsigned addr = (unsigned)__cvta_generic_to_shared(p);
    asm volatile("ldmatrix.sync.aligned.m8n8.x4.shared.b16 {%0,%1,%2,%3}, [%4];"
        : "=r"(r[0]), "=r"(r[1]), "=r"(r[2]), "=r"(r[3]) : "r"(addr));
}

__device__ __forceinline__ void mma16816(float* c, const unsigned* a, unsigned b0, unsigned b1) {
    asm volatile("mma.sync.aligned.m16n8k16.row.col.f32.bf16.bf16.f32 "
        "{%0,%1,%2,%3}, {%4,%5,%6,%7}, {%8,%9}, {%0,%1,%2,%3};"
        : "+f"(c[0]), "+f"(c[1]), "+f"(c[2]), "+f"(c[3])
        : "r"(a[0]), "r"(a[1]), "r"(a[2]), "r"(a[3]), "r"(b0), "r"(b1));
}

// split fp32 -> (hi, lo) bf16 pair-packed, store as uint2 (4 elems)
__device__ __forceinline__ void split_store(__nv_bfloat16* hi_base, __nv_bfloat16* lo_base,
                                            int off, float4 v) {
    __nv_bfloat16 hx = __float2bfloat16(v.x), hy = __float2bfloat16(v.y);
    __nv_bfloat16 hz = __float2bfloat16(v.z), hw = __float2bfloat16(v.w);
    __nv_bfloat16 lx = __float2bfloat16(v.x - __bfloat162float(hx));
    __nv_bfloat16 ly = __float2bfloat16(v.y - __bfloat162float(hy));
    __nv_bfloat16 lz = __float2bfloat16(v.z - __bfloat162float(hz));
    __nv_bfloat16 lw = __float2bfloat16(v.w - __bfloat162float(hw));
    *(uint2*)(hi_base + off) = make_uint2(pack2(hx, hy), pack2(hz, hw));
    *(uint2*)(lo_base + off) = make_uint2(pack2(lx, ly), pack2(lz, lw));
}

// ---------------- tensor-core GEMM ----------------
// C[M,N] = op(A)[M,K] @ W[N,K]^T + bias
// MODE 0: A binarized (exact bf16), W split hi/lo  -> acc = Ab*Whi + Ab*Wlo      (exact-ish)
// MODE 1: A and W both split; acc = Ahi*Whi + Ahi*Wlo + Alo*Whi; mish epilogue
template<int MODE>
__global__ __launch_bounds__(256)
void mma_gemm(const float* __restrict__ A, const float* __restrict__ W,
              const float* __restrict__ bias, float* __restrict__ C)
{
    extern __shared__ char smem_raw[];
    __nv_bfloat16* smem = (__nv_bfloat16*)smem_raw;
    const int NT    = (MODE == 0) ? 3 : 4;
    const int STAGE = NT * BM * KP;

    const int tid  = threadIdx.x;
    const int lane = tid & 31;
    const int wid  = tid >> 5;
    const int wm   = wid & 1;     // 2 warp rows (64 rows each)
    const int wn   = wid >> 1;    // 4 warp cols (32 cols each)
    const int bm   = blockIdx.y * BM;
    const int bn   = blockIdx.x * BN;

    float acc[4][4][4];
#pragma unroll
    for (int i = 0; i < 4; i++)
#pragma unroll
        for (int j = 0; j < 4; j++)
#pragma unroll
            for (int r = 0; r < 4; r++) acc[i][j][r] = 0.f;

    float4 ra[4], rw[4];

    auto LOAD = [&](int k0) {
#pragma unroll
        for (int i = 0; i < 4; i++) {
            int id  = i * 256 + tid;
            int row = id >> 3;
            int c4  = (id & 7) * 4;
            ra[i] = *(const float4*)(A + (size_t)(bm + row) * D_ + k0 + c4);
            rw[i] = *(const float4*)(W + (size_t)(bn + row) * D_ + k0 + c4);
        }
    };

    auto STORE = [&](int buf) {
        __nv_bfloat16* base = smem + buf * STAGE;
#pragma unroll
        for (int i = 0; i < 4; i++) {
            int id  = i * 256 + tid;
            int row = id >> 3;
            int c4  = (id & 7) * 4;
            int off = row * KP + c4;
            if (MODE == 0) {
                unsigned p0 = pack2(__float2bfloat16(ra[i].x >= 2.f ? 1.f : 0.f),
                                    __float2bfloat16(ra[i].y >= 2.f ? 1.f : 0.f));
                unsigned p1 = pack2(__float2bfloat16(ra[i].z >= 2.f ? 1.f : 0.f),
                                    __float2bfloat16(ra[i].w >= 2.f ? 1.f : 0.f));
                *(uint2*)(base + off) = make_uint2(p0, p1);
                split_store(base + 1 * BM * KP, base + 2 * BM * KP, off, rw[i]);
            } else {
                split_store(base + 0 * BM * KP, base + 1 * BM * KP, off, ra[i]);
                split_store(base + 2 * BM * KP, base + 3 * BM * KP, off, rw[i]);
            }
        }
    };

    LOAD(0);
    STORE(0);
    __syncthreads();

    const int NCH = D_ / BK;   // 32
    for (int c = 0; c < NCH; c++) {
        if (c + 1 < NCH) LOAD((c + 1) * BK);

        const __nv_bfloat16* base = smem + (c & 1) * STAGE;
        const __nv_bfloat16* tA  = base;                                 // MODE1: A_hi
        const __nv_bfloat16* tAl = base + 1 * BM * KP;                   // MODE1 only
        const __nv_bfloat16* tWh = base + (MODE == 0 ? 1 : 2) * BM * KP;
        const __nv_bfloat16* tWl = base + (MODE == 0 ? 2 : 3) * BM * KP;

        const int lr  = lane & 15;
        const int lc8 = (lane >> 4) * 8;

#pragma unroll
        for (int s = 0; s < 2; s++) {
            const int cs = s * 16 + lc8;
            unsigned af[4][4];
#pragma unroll
            for (int mi = 0; mi < 4; mi++)
                ldm4(af[mi], tA + (wm * 64 + mi * 16 + lr) * KP + cs);
            unsigned bh[2][4], bl[2][4];
#pragma unroll
            for (int nb = 0; nb < 2; nb++) {
                ldm4(bh[nb], tWh + (wn * 32 + nb * 16 + lr) * KP + cs);
                ldm4(bl[nb], tWl + (wn * 32 + nb * 16 + lr) * KP + cs);
            }
            unsigned al[4][4];
            if (MODE == 1) {
#pragma unroll
                for (int mi = 0; mi < 4; mi++)
                    ldm4(al[mi], tAl + (wm * 64 + mi * 16 + lr) * KP + cs);
            }
#pragma unroll
            for (int mi = 0; mi < 4; mi++) {
#pragma unroll
                for (int nj = 0; nj < 4; nj++) {
                    const int nb = nj >> 1, sl = nj & 1;
                    mma16816(acc[mi][nj], af[mi], bh[nb][sl], bh[nb][2 + sl]);
                    mma16816(acc[mi][nj], af[mi], bl[nb][sl], bl[nb][2 + sl]);
                    if (MODE == 1)
                        mma16816(acc[mi][nj], al[mi], bh[nb][sl], bh[nb][2 + sl]);
                }
            }
        }

        if (c + 1 < NCH) STORE((c + 1) & 1);
        __syncthreads();
    }

    // epilogue
    const int g = lane >> 2, tg = lane & 3;
#pragma unroll
    for (int mi = 0; mi < 4; mi++) {
#pragma unroll
        for (int nj = 0; nj < 4; nj++) {
            int m0 = bm + wm * 64 + mi * 16 + g;
            int n0 = bn + wn * 32 + nj * 8 + tg * 2;
            float2 bs = *(const float2*)(bias + n0);
            float v0 = acc[mi][nj][0] + bs.x;
            float v1 = acc[mi][nj][1] + bs.y;
            float v2 = acc[mi][nj][2] + bs.x;
            float v3 = acc[mi][nj][3] + bs.y;
            if (MODE == 1) {
                float2 r0 = *(const float2*)(A + (size_t)m0 * D_ + n0);
                float2 r1 = *(const float2*)(A + (size_t)(m0 + 8) * D_ + n0);
                v0 = r0.x + mishf(v0);
                v1 = r0.y + mishf(v1);
                v2 = r1.x + mishf(v2);
                v3 = r1.y + mishf(v3);
            }
            *(float2*)(C + (size_t)m0 * D_ + n0)       = make_float2(v0, v1);
            *(float2*)(C + (size_t)(m0 + 8) * D_ + n0) = make_float2(v2, v3);
        }
    }
}

// ---------------- LayerNorm + LIF + bit-pack ----------------
__global__ __launch_bounds__(256)
void ln_lif_pack(const float* __restrict__ X,
                 const float* __restrict__ gamma, const float* __restrict__ beta,
                 unsigned* __restrict__ bits)
{
    const int row  = blockIdx.x;
    const int t    = threadIdx.x;
    const int lane = t & 31;
    const int wid  = t >> 5;

    const float* xr = X + (size_t)row * D_;

    float x[4];
    float s = 0.f, sq = 0.f;
#pragma unroll
    for (int i = 0; i < 4; i++) {
        x[i] = xr[i * 256 + t];
        s  += x[i];
        sq += x[i] * x[i];
    }
#pragma unroll
    for (int off = 16; off > 0; off >>= 1) {
        s  += __shfl_xor_sync(0xffffffffu, s,  off);
        sq += __shfl_xor_sync(0xffffffffu, sq, off);
    }
    __shared__ float ss[8], sqq[8];
    __shared__ float s_mu, s_rs;
    if (lane == 0) { ss[wid] = s; sqq[wid] = sq; }
    __syncthreads();
    if (wid == 0) {
        float a = (lane < 8) ? ss[lane]  : 0.f;
        float b = (lane < 8) ? sqq[lane] : 0.f;
#pragma unroll
        for (int off = 4; off > 0; off >>= 1) {
            a += __shfl_xor_sync(0xffffffffu, a, off);
            b += __shfl_xor_sync(0xffffffffu, b, off);
        }
        if (lane == 0) {
            float mu  = a * (1.f / D_);
            float var = b * (1.f / D_) - mu * mu;
            s_mu = mu;
            s_rs = rsqrtf(var + EPS_);
        }
    }
    __syncthreads();
    const float mu = s_mu, rs = s_rs;

#pragma unroll
    for (int i = 0; i < 4; i++) {
        int d = i * 256 + t;
        float y = (x[i] - mu) * rs * gamma[d] + beta[d];
        unsigned word = __ballot_sync(0xffffffffu, y >= 2.0f);
        if (lane == 0) bits[(size_t)row * 32 + i * 8 + wid] = word;
    }
}

// ---------------- flash attention: popcount QK + packed f32x2 PV ----------------
__global__ __launch_bounds__(128)
void attn_kernel(const unsigned* __restrict__ qbits, const unsigned* __restrict__ kbits,
                 const float* __restrict__ V, const float* __restrict__ mask,
                 float* __restrict__ out)
{
    const int qblk = blockIdx.x;
    const int h    = blockIdx.y;
    const int b    = blockIdx.z;
    const int t    = threadIdx.x;
    const int qr   = qblk * 128 + t;

    __shared__ float    sV[32][64];
    __shared__ float    sM[128][33];
    __shared__ unsigned sKb[32][2];

    const unsigned q0 = qbits[((size_t)(b * S_ + qr)) * 32 + h * 2 + 0];
    const unsigned q1 = qbits[((size_t)(b * S_ + qr)) * 32 + h * 2 + 1];

    unsigned long long acc2[32];
#pragma unroll
    for (int i = 0; i < 32; i++) acc2[i] = 0ull;   // packed (0.f, 0.f)
    float ssum = 0.f;

    const float* maskB = mask + (size_t)b * S_ * S_;

    for (int k0 = 0; k0 < S_; k0 += 32) {
        if (t < 64) {
            int j = t >> 1, w = t & 1;
            sKb[j][w] = kbits[((size_t)(b * S_ + k0 + j)) * 32 + h * 2 + w];
        }
        const float4* Vg = (const float4*)(V + ((size_t)(b * S_ + k0)) * D_ + h * HD_);
#pragma unroll
        for (int i = 0; i < 4; i++) {
            int id = t + 128 * i;
            int j  = id >> 4, d4 = id & 15;
            ((float4*)&sV[j][0])[d4] = Vg[(size_t)j * 256 + d4];
        }
#pragma unroll
        for (int i = 0; i < 32; i++) {
            int r = i * 4 + (t >> 5);
            int c = t & 31;
            sM[r][c] = maskB[(size_t)(qblk * 128 + r) * S_ + k0 + c];
        }
        __syncthreads();
#pragma unroll
        for (int j = 0; j < 32; j++) {
            int sc = __popc(q0 & sKb[j][0]) + __popc(q1 & sKb[j][1]);
            float e = __expf((float)sc * 0.125f * sM[t][j]);
            ssum += e;
            unsigned long long e2;
            asm("mov.b64 %0, {%1, %1};" : "=l"(e2) : "f"(e));
            const unsigned long long* vr = (const unsigned long long*)(&sV[j][0]);
#pragma unroll
            for (int d = 0; d < 32; d++) {
                asm("fma.rn.f32x2 %0, %1, %2, %0;"
                    : "+l"(acc2[d]) : "l"(e2), "l"(vr[d]));
            }
        }
        __syncthreads();
    }
    const float inv = 1.f / ssum;
    float2* og = (float2*)(out + ((size_t)(b * S_ + qr)) * D_ + h * HD_);
#pragma unroll
    for (int d = 0; d < 32; d++) {
        float lo, hi;
        asm("mov.b64 {%0, %1}, %2;" : "=f"(lo), "=f"(hi) : "l"(acc2[d]));
        og[d] = make_float2(lo * inv, hi * inv);
    }
}

// ---------------- launch ----------------
extern "C" void kernel_launch(void* const* d_in, const int* in_sizes, int n_in,
                              void* d_out, int out_size)
{
    const float* Q   = (const float*)d_in[0];
    const float* K_  = (const float*)d_in[1];
    const float* adj = (const float*)d_in[2];
    const float* Wq  = (const float*)d_in[3];
    const float* bq  = (const float*)d_in[4];
    const float* Wk  = (const float*)d_in[5];
    const float* bk  = (const float*)d_in[6];
    const float* Wv  = (const float*)d_in[7];
    const float* bv  = (const float*)d_in[8];
    const float* Wo  = (const float*)d_in[9];
    const float* bo  = (const float*)d_in[10];
    const float* gq  = (const float*)d_in[11];
    const float* beq = (const float*)d_in[12];
    const float* gk  = (const float*)d_in[13];
    const float* bek = (const float*)d_in[14];
    float* out = (float*)d_out;

    float *Xq, *Xk, *Vb, *At;
    unsigned *qb, *kb;
    cudaGetSymbolAddress((void**)&Xq, g_Xq);
    cudaGetSymbolAddress((void**)&Xk, g_Xk);
    cudaGetSymbolAddress((void**)&Vb, g_V);
    cudaGetSymbolAddress((void**)&At, g_At);
    cudaGetSymbolAddress((void**)&qb, g_qb);
    cudaGetSymbolAddress((void**)&kb, g_kb);

    const int smem0 = 2 * 3 * BM * KP * 2;   // 61440
    const int smem1 = 2 * 4 * BM * KP * 2;   // 81920
    cudaFuncSetAttribute(mma_gemm<0>, cudaFuncAttributeMaxDynamicSharedMemorySize, smem0);
    cudaFuncSetAttribute(mma_gemm<1>, cudaFuncAttributeMaxDynamicSharedMemorySize, smem1);

    dim3 gg(D_ / BN, ROWS / BM);   // (8, 64)

    mma_gemm<0><<<gg, 256, smem0>>>(Q,  Wq, bq, Xq);
    mma_gemm<0><<<gg, 256, smem0>>>(K_, Wk, bk, Xk);
    mma_gemm<0><<<gg, 256, smem0>>>(K_, Wv, bv, Vb);

    ln_lif_pack<<<ROWS, 256>>>(Xq, gq, beq, qb);
    ln_lif_pack<<<ROWS, 256>>>(Xk, gk, bek, kb);

    attn_kernel<<<dim3(8, H_, B_), 128>>>(qb, kb, Vb, adj, At);

    mma_gemm<1><<<gg, 256, smem1>>>(At, Wo, bo, out);
}

// round 4
// speedup vs baseline: 2.0260x; 1.0676x over previous
#include <cuda_runtime.h>
#include <cuda_bf16.h>
#include <cstdint>

// Problem constants
#define B_   8
#define S_   1024
#define D_   1024
#define H_   16
#define HD_  64
#define ROWS (B_ * S_)
#define EPS_ 1e-5f

// GEMM tiling: CTA tile 128x128, K chunk 64 bf16 (= 128-byte SW128 rows)
#define BKC    64
#define TILEB  16384           // 128 rows * 128 bytes
#define NCH    (D_ / BKC)      // 16

#define SW128(x) ((x) ^ (((x) >> 3) & 0x70))

// ---------------- scratch (device globals) ----------------
__device__ float         g_Xq[ROWS * D_];
__device__ float         g_Xk[ROWS * D_];
__device__ float         g_V [ROWS * D_];
__device__ float         g_At[ROWS * D_];
__device__ __nv_bfloat16 g_Qb[ROWS * D_];
__device__ __nv_bfloat16 g_Kb[ROWS * D_];
__device__ __nv_bfloat16 g_Ath[ROWS * D_];
__device__ __nv_bfloat16 g_Atl[ROWS * D_];
__device__ __nv_bfloat16 g_Wh[4][D_ * D_];
__device__ __nv_bfloat16 g_Wl[4][D_ * D_];
__device__ unsigned      g_qb[ROWS * 32];
__device__ unsigned      g_kb[ROWS * 32];

// ---------------- helpers ----------------
__device__ __forceinline__ uint32_t smem_u32(const void* p) {
    return (uint32_t)__cvta_generic_to_shared(p);
}
__device__ __forceinline__ float mishf(float x) {
    float sp = (x > 20.f) ? x : log1pf(__expf(x));
    return x * tanhf(sp);
}
__device__ __forceinline__ unsigned pack2(__nv_bfloat16 a, __nv_bfloat16 b) {
    __nv_bfloat162 t = __halves2bfloat162(a, b);
    return *reinterpret_cast<unsigned*>(&t);
}
__device__ __forceinline__ uint2 split_hi(float4 v, float4& rem) {
    __nv_bfloat16 hx = __float2bfloat16(v.x), hy = __float2bfloat16(v.y);
    __nv_bfloat16 hz = __float2bfloat16(v.z), hw = __float2bfloat16(v.w);
    rem.x = v.x - __bfloat162float(hx);
    rem.y = v.y - __bfloat162float(hy);
    rem.z = v.z - __bfloat162float(hz);
    rem.w = v.w - __bfloat162float(hw);
    return make_uint2(pack2(hx, hy), pack2(hz, hw));
}
__device__ __forceinline__ void ldm4(unsigned* r, const void* p) {
    unsigned addr = smem_u32(p);
    asm volatile("ldmatrix.sync.aligned.m8n8.x4.shared.b16 {%0,%1,%2,%3}, [%4];"
        : "=r"(r[0]), "=r"(r[1]), "=r"(r[2]), "=r"(r[3]) : "r"(addr));
}
__device__ __forceinline__ void mma16816(float* c, const unsigned* a, unsigned b0, unsigned b1) {
    asm volatile("mma.sync.aligned.m16n8k16.row.col.f32.bf16.bf16.f32 "
        "{%0,%1,%2,%3}, {%4,%5,%6,%7}, {%8,%9}, {%0,%1,%2,%3};"
        : "+f"(c[0]), "+f"(c[1]), "+f"(c[2]), "+f"(c[3])
        : "r"(a[0]), "r"(a[1]), "r"(a[2]), "r"(a[3]), "r"(b0), "r"(b1));
}
__device__ __forceinline__ void cpa16(uint32_t sa, const void* g) {
    asm volatile("cp.async.cg.shared.global [%0], [%1], 16;" :: "r"(sa), "l"(g));
}

// ---------------- prep kernels ----------------
__global__ __launch_bounds__(256)
void prep_split(const float* __restrict__ W,
                __nv_bfloat16* __restrict__ hi, __nv_bfloat16* __restrict__ lo)
{
    int i = blockIdx.x * blockDim.x + threadIdx.x;   // float4 index
    float4 v = ((const float4*)W)[i];
    float4 rem, d;
    uint2 h = split_hi(v, rem);
    uint2 l = split_hi(rem, d);
    ((uint2*)hi)[i] = h;
    ((uint2*)lo)[i] = l;
}

__global__ __launch_bounds__(256)
void prep_bin(const float* __restrict__ X, __nv_bfloat16* __restrict__ Y)
{
    int i = blockIdx.x * blockDim.x + threadIdx.x;   // float4 index
    float4 v = ((const float4*)X)[i];
    unsigned p0 = pack2(__float2bfloat16(v.x >= 2.f ? 1.f : 0.f),
                        __float2bfloat16(v.y >= 2.f ? 1.f : 0.f));
    unsigned p1 = pack2(__float2bfloat16(v.z >= 2.f ? 1.f : 0.f),
                        __float2bfloat16(v.w >= 2.f ? 1.f : 0.f));
    ((uint2*)Y)[i] = make_uint2(p0, p1);
}

// ---------------- bf16 HMMA GEMM ----------------
// MODE 0: acc = A0 @ (Wh + Wl)^T           (A0 = binarized input, exact bf16)
// MODE 1: acc = A0@Wh^T + A0@Wl^T + A1@Wh^T ; out = resid + mish(acc + bias)
template<int MODE>
__global__ __launch_bounds__(256, 1)
void hgemm(const __nv_bfloat16* __restrict__ A0, const __nv_bfloat16* __restrict__ A1,
           const __nv_bfloat16* __restrict__ Wh, const __nv_bfloat16* __restrict__ Wl,
           const float* __restrict__ bias, const float* __restrict__ resid,
           float* __restrict__ C)
{
    constexpr int NT = MODE ? 4 : 3;
    extern __shared__ char raw[];
    char* base = (char*)(((uintptr_t)raw + 1023) & ~(uintptr_t)1023);

    const int tid  = threadIdx.x;
    const int lane = tid & 31;
    const int wid  = tid >> 5;
    const int wm   = wid & 1;
    const int wn   = wid >> 1;
    const int bm   = blockIdx.y * 128;
    const int bn   = blockIdx.x * 128;

    float acc[4][4][4];
#pragma unroll
    for (int i = 0; i < 4; i++)
#pragma unroll
        for (int j = 0; j < 4; j++)
#pragma unroll
            for (int r = 0; r < 4; r++) acc[i][j][r] = 0.f;

    auto load = [&](int c) {
        char* st = base + (c & 1) * NT * TILEB;
        const int k0 = c * BKC;
#pragma unroll
        for (int t = 0; t < NT; t++) {
            const __nv_bfloat16* src;
            int rb;
            if (MODE == 0) {
                src = (t == 0) ? A0 : ((t == 1) ? Wh : Wl);
                rb  = (t == 0) ? bm : bn;
            } else {
                src = (t == 0) ? A0 : ((t == 1) ? A1 : ((t == 2) ? Wh : Wl));
                rb  = (t < 2) ? bm : bn;
            }
#pragma unroll
            for (int it = 0; it < 4; it++) {
                int id  = it * 256 + tid;
                int row = id >> 3;
                int ch  = id & 7;
                uint32_t sa = smem_u32(st + t * TILEB + SW128(row * 128 + ch * 16));
                cpa16(sa, src + (size_t)(rb + row) * D_ + k0 + ch * 8);
            }
        }
        asm volatile("cp.async.commit_group;" ::: "memory");
    };

    load(0);
    for (int c = 0; c < NCH; c++) {
        if (c + 1 < NCH) {
            load(c + 1);
            asm volatile("cp.async.wait_group 1;" ::: "memory");
        } else {
            asm volatile("cp.async.wait_group 0;" ::: "memory");
        }
        __syncthreads();

        const char* st  = base + (c & 1) * NT * TILEB;
        const char* tA  = st;
        const char* tAl = st + TILEB;
        const char* tWh = st + (MODE ? 2 : 1) * TILEB;
        const char* tWl = st + (MODE ? 3 : 2) * TILEB;

        const int lr  = lane & 15;
        const int lc8 = (lane >> 4) * 8;

#pragma unroll
        for (int ks = 0; ks < 4; ks++) {
            const int cs2 = (ks * 16 + lc8) * 2;
            unsigned af[4][4];
#pragma unroll
            for (int mi = 0; mi < 4; mi++)
                ldm4(af[mi], tA + SW128((wm * 64 + mi * 16 + lr) * 128 + cs2));
            unsigned bh[2][4], bl[2][4];
#pragma unroll
            for (int nb = 0; nb < 2; nb++) {
                ldm4(bh[nb], tWh + SW128((wn * 32 + nb * 16 + lr) * 128 + cs2));
                ldm4(bl[nb], tWl + SW128((wn * 32 + nb * 16 + lr) * 128 + cs2));
            }
            unsigned al[4][4];
            if (MODE == 1) {
#pragma unroll
                for (int mi = 0; mi < 4; mi++)
                    ldm4(al[mi], tAl + SW128((wm * 64 + mi * 16 + lr) * 128 + cs2));
            }
#pragma unroll
            for (int mi = 0; mi < 4; mi++) {
#pragma unroll
                for (int nj = 0; nj < 4; nj++) {
                    const int nb = nj >> 1, sl = nj & 1;
                    mma16816(acc[mi][nj], af[mi], bh[nb][sl], bh[nb][2 + sl]);
                    mma16816(acc[mi][nj], af[mi], bl[nb][sl], bl[nb][2 + sl]);
                    if (MODE == 1)
                        mma16816(acc[mi][nj], al[mi], bh[nb][sl], bh[nb][2 + sl]);
                }
            }
        }
        __syncthreads();
    }

    // epilogue
    const int g = lane >> 2, tg = lane & 3;
#pragma unroll
    for (int mi = 0; mi < 4; mi++) {
#pragma unroll
        for (int nj = 0; nj < 4; nj++) {
            int m0 = bm + wm * 64 + mi * 16 + g;
            int n0 = bn + wn * 32 + nj * 8 + tg * 2;
            float2 bs = *(const float2*)(bias + n0);
            float v0 = acc[mi][nj][0] + bs.x;
            float v1 = acc[mi][nj][1] + bs.y;
            float v2 = acc[mi][nj][2] + bs.x;
            float v3 = acc[mi][nj][3] + bs.y;
            if (MODE == 1) {
                float2 r0 = *(const float2*)(resid + (size_t)m0 * D_ + n0);
                float2 r1 = *(const float2*)(resid + (size_t)(m0 + 8) * D_ + n0);
                v0 = r0.x + mishf(v0);
                v1 = r0.y + mishf(v1);
                v2 = r1.x + mishf(v2);
                v3 = r1.y + mishf(v3);
            }
            *(float2*)(C + (size_t)m0 * D_ + n0)       = make_float2(v0, v1);
            *(float2*)(C + (size_t)(m0 + 8) * D_ + n0) = make_float2(v2, v3);
        }
    }
}

// ---------------- LayerNorm + LIF + bit-pack ----------------
__global__ __launch_bounds__(256)
void ln_lif_pack(const float* __restrict__ X,
                 const float* __restrict__ gamma, const float* __restrict__ beta,
                 unsigned* __restrict__ bits)
{
    const int row  = blockIdx.x;
    const int t    = threadIdx.x;
    const int lane = t & 31;
    const int wid  = t >> 5;

    const float* xr = X + (size_t)row * D_;

    float x[4];
    float s = 0.f, sq = 0.f;
#pragma unroll
    for (int i = 0; i < 4; i++) {
        x[i] = xr[i * 256 + t];
        s  += x[i];
        sq += x[i] * x[i];
    }
#pragma unroll
    for (int off = 16; off > 0; off >>= 1) {
        s  += __shfl_xor_sync(0xffffffffu, s,  off);
        sq += __shfl_xor_sync(0xffffffffu, sq, off);
    }
    __shared__ float ss[8], sqq[8];
    __shared__ float s_mu, s_rs;
    if (lane == 0) { ss[wid] = s; sqq[wid] = sq; }
    __syncthreads();
    if (wid == 0) {
        float a = (lane < 8) ? ss[lane]  : 0.f;
        float b = (lane < 8) ? sqq[lane] : 0.f;
#pragma unroll
        for (int off = 4; off > 0; off >>= 1) {
            a += __shfl_xor_sync(0xffffffffu, a, off);
            b += __shfl_xor_sync(0xffffffffu, b, off);
        }
        if (lane == 0) {
            float mu  = a * (1.f / D_);
            float var = b * (1.f / D_) - mu * mu;
            s_mu = mu;
            s_rs = rsqrtf(var + EPS_);
        }
    }
    __syncthreads();
    const float mu = s_mu, rs = s_rs;

#pragma unroll
    for (int i = 0; i < 4; i++) {
        int d = i * 256 + t;
        float y = (x[i] - mu) * rs * gamma[d] + beta[d];
        unsigned word = __ballot_sync(0xffffffffu, y >= 2.0f);
        if (lane == 0) bits[(size_t)row * 32 + i * 8 + wid] = word;
    }
}

// ---------------- flash attention: popcount QK + packed f32x2 PV ----------------
__global__ __launch_bounds__(128)
void attn_kernel(const unsigned* __restrict__ qbits, const unsigned* __restrict__ kbits,
                 const float* __restrict__ V, const float* __restrict__ mask,
                 float* __restrict__ out,
                 __nv_bfloat16* __restrict__ outh, __nv_bfloat16* __restrict__ outl)
{
    const int qblk = blockIdx.x;
    const int h    = blockIdx.y;
    const int b    = blockIdx.z;
    const int t    = threadIdx.x;
    const int qr   = qblk * 128 + t;

    __shared__ float    sV[32][64];
    __shared__ float    sM[128][33];
    __shared__ unsigned sKb[32][2];

    const unsigned q0 = qbits[((size_t)(b * S_ + qr)) * 32 + h * 2 + 0];
    const unsigned q1 = qbits[((size_t)(b * S_ + qr)) * 32 + h * 2 + 1];

    unsigned long long acc2[32];
#pragma unroll
    for (int i = 0; i < 32; i++) acc2[i] = 0ull;
    float ssum = 0.f;

    const float* maskB = mask + (size_t)b * S_ * S_;

    for (int k0 = 0; k0 < S_; k0 += 32) {
        if (t < 64) {
            int j = t >> 1, w = t & 1;
            sKb[j][w] = kbits[((size_t)(b * S_ + k0 + j)) * 32 + h * 2 + w];
        }
        const float4* Vg = (const float4*)(V + ((size_t)(b * S_ + k0)) * D_ + h * HD_);
#pragma unroll
        for (int i = 0; i < 4; i++) {
            int id = t + 128 * i;
            int j  = id >> 4, d4 = id & 15;
            ((float4*)&sV[j][0])[d4] = Vg[(size_t)j * 256 + d4];
        }
#pragma unroll
        for (int i = 0; i < 32; i++) {
            int r = i * 4 + (t >> 5);
            int c = t & 31;
            sM[r][c] = maskB[(size_t)(qblk * 128 + r) * S_ + k0 + c];
        }
        __syncthreads();
#pragma unroll
        for (int j = 0; j < 32; j++) {
            int sc = __popc(q0 & sKb[j][0]) + __popc(q1 & sKb[j][1]);
            float e = __expf((float)sc * 0.125f * sM[t][j]);
            ssum += e;
            unsigned long long e2;
            asm("mov.b64 %0, {%1, %1};" : "=l"(e2) : "f"(e));
            const unsigned long long* vr = (const unsigned long long*)(&sV[j][0]);
#pragma unroll
            for (int d = 0; d < 32; d++) {
                asm("fma.rn.f32x2 %0, %1, %2, %0;"
                    : "+l"(acc2[d]) : "l"(e2), "l"(vr[d]));
            }
        }
        __syncthreads();
    }
    const float inv = 1.f / ssum;
    const size_t off = ((size_t)(b * S_ + qr)) * D_ + h * HD_;
    float2*   og = (float2*)(out + off);
    unsigned* oh = (unsigned*)(outh + off);
    unsigned* ol = (unsigned*)(outl + off);
#pragma unroll
    for (int d = 0; d < 32; d++) {
        float lo, hi;
        asm("mov.b64 {%0, %1}, %2;" : "=f"(lo), "=f"(hi) : "l"(acc2[d]));
        float ox = lo * inv, oy = hi * inv;
        og[d] = make_float2(ox, oy);
        __nv_bfloat16 hx = __float2bfloat16(ox), hy = __float2bfloat16(oy);
        oh[d] = pack2(hx, hy);
        ol[d] = pack2(__float2bfloat16(ox - __bfloat162float(hx)),
                      __float2bfloat16(oy - __bfloat162float(hy)));
    }
}

// ---------------- launch ----------------
extern "C" void kernel_launch(void* const* d_in, const int* in_sizes, int n_in,
                              void* d_out, int out_size)
{
    const float* Q   = (const float*)d_in[0];
    const float* K_  = (const float*)d_in[1];
    const float* adj = (const float*)d_in[2];
    const float* Wq  = (const float*)d_in[3];
    const float* bq  = (const float*)d_in[4];
    const float* Wk  = (const float*)d_in[5];
    const float* bk  = (const float*)d_in[6];
    const float* Wv  = (const float*)d_in[7];
    const float* bv  = (const float*)d_in[8];
    const float* Wo  = (const float*)d_in[9];
    const float* bo  = (const float*)d_in[10];
    const float* gq  = (const float*)d_in[11];
    const float* beq = (const float*)d_in[12];
    const float* gk  = (const float*)d_in[13];
    const float* bek = (const float*)d_in[14];
    float* out = (float*)d_out;

    float *Xq, *Xk, *Vb, *At;
    __nv_bfloat16 *Qb, *Kb, *Ath, *Atl, *Wh, *Wl;
    unsigned *qb, *kb;
    cudaGetSymbolAddress((void**)&Xq, g_Xq);
    cudaGetSymbolAddress((void**)&Xk, g_Xk);
    cudaGetSymbolAddress((void**)&Vb, g_V);
    cudaGetSymbolAddress((void**)&At, g_At);
    cudaGetSymbolAddress((void**)&Qb, g_Qb);
    cudaGetSymbolAddress((void**)&Kb, g_Kb);
    cudaGetSymbolAddress((void**)&Ath, g_Ath);
    cudaGetSymbolAddress((void**)&Atl, g_Atl);
    cudaGetSymbolAddress((void**)&Wh, g_Wh);
    cudaGetSymbolAddress((void**)&Wl, g_Wl);
    cudaGetSymbolAddress((void**)&qb, g_qb);
    cudaGetSymbolAddress((void**)&kb, g_kb);

    const int smem0 = 2 * 3 * TILEB + 1024;   // 99328
    const int smem1 = 2 * 4 * TILEB + 1024;   // 132096
    cudaFuncSetAttribute(hgemm<0>, cudaFuncAttributeMaxDynamicSharedMemorySize, smem0);
    cudaFuncSetAttribute(hgemm<1>, cudaFuncAttributeMaxDynamicSharedMemorySize, smem1);

    const int WELEM = D_ * D_;
    // weight splits (hi/lo) — 1M elems each, float4-granular
    prep_split<<<WELEM / 4 / 256, 256>>>(Wq, Wh + 0 * WELEM, Wl + 0 * WELEM);
    prep_split<<<WELEM / 4 / 256, 256>>>(Wk, Wh + 1 * WELEM, Wl + 1 * WELEM);
    prep_split<<<WELEM / 4 / 256, 256>>>(Wv, Wh + 2 * WELEM, Wl + 2 * WELEM);
    prep_split<<<WELEM / 4 / 256, 256>>>(Wo, Wh + 3 * WELEM, Wl + 3 * WELEM);
    // binarize inputs
    prep_bin<<<ROWS * D_ / 4 / 256, 256>>>(Q,  Qb);
    prep_bin<<<ROWS * D_ / 4 / 256, 256>>>(K_, Kb);

    dim3 gg(D_ / 128, ROWS / 128);   // (8, 64)

    hgemm<0><<<gg, 256, smem0>>>(Qb, nullptr, Wh + 0 * WELEM, Wl + 0 * WELEM, bq, nullptr, Xq);
    hgemm<0><<<gg, 256, smem0>>>(Kb, nullptr, Wh + 1 * WELEM, Wl + 1 * WELEM, bk, nullptr, Xk);
    hgemm<0><<<gg, 256, smem0>>>(Kb, nullptr, Wh + 2 * WELEM, Wl + 2 * WELEM, bv, nullptr, Vb);

    ln_lif_pack<<<ROWS, 256>>>(Xq, gq, beq, qb);
    ln_lif_pack<<<ROWS, 256>>>(Xk, gk, bek, kb);

    attn_kernel<<<dim3(8, H_, B_), 128>>>(qb, kb, Vb, adj, At, Ath, Atl);

    hgemm<1><<<gg, 256, smem1>>>(Ath, Atl, Wh + 3 * WELEM, Wl + 3 * WELEM, bo, At, out);
}

// round 5
// speedup vs baseline: 2.3374x; 1.1537x over previous
#include <cuda_runtime.h>
#include <cuda_fp16.h>
#include <cstdint>

// Problem constants
#define B_   8
#define S_   1024
#define D_   1024
#define H_   16
#define HD_  64
#define ROWS (B_ * S_)
#define EPS_ 1e-5f

// GEMM tiling: CTA tile 128x128, K chunk 64 fp16 (= 128-byte SW128 rows)
#define BKC    64
#define TILEB  16384           // 128 rows * 128 bytes
#define NCH    (D_ / BKC)      // 16

#define SW128(x) ((x) ^ (((x) >> 3) & 0x70))

// ---------------- scratch (device globals) ----------------
__device__ float  g_Xq[ROWS * D_];
__device__ float  g_Xk[ROWS * D_];
__device__ float  g_V [ROWS * D_];
__device__ float  g_At[ROWS * D_];
__device__ __half g_Qb[ROWS * D_];
__device__ __half g_Kb[ROWS * D_];
__device__ __half g_Ath[ROWS * D_];
__device__ __half g_Wqh[D_ * D_];
__device__ __half g_Wql[D_ * D_];
__device__ __half g_Wkh[D_ * D_];
__device__ __half g_Wkl[D_ * D_];
__device__ __half g_Wv1[D_ * D_];
__device__ __half g_Wo1[D_ * D_];
__device__ unsigned g_qb[ROWS * 32];
__device__ unsigned g_kb[ROWS * 32];

// ---------------- helpers ----------------
__device__ __forceinline__ uint32_t smem_u32(const void* p) {
    return (uint32_t)__cvta_generic_to_shared(p);
}
__device__ __forceinline__ float mishf(float x) {
    float sp = (x > 20.f) ? x : log1pf(__expf(x));
    return x * tanhf(sp);
}
__device__ __forceinline__ unsigned packh2(__half a, __half b) {
    __half2 t = __halves2half2(a, b);
    return *reinterpret_cast<unsigned*>(&t);
}
__device__ __forceinline__ void ldm4(unsigned* r, const void* p) {
    unsigned addr = smem_u32(p);
    asm volatile("ldmatrix.sync.aligned.m8n8.x4.shared.b16 {%0,%1,%2,%3}, [%4];"
        : "=r"(r[0]), "=r"(r[1]), "=r"(r[2]), "=r"(r[3]) : "r"(addr));
}
__device__ __forceinline__ void mma16816(float* c, const unsigned* a, unsigned b0, unsigned b1) {
    asm volatile("mma.sync.aligned.m16n8k16.row.col.f32.f16.f16.f32 "
        "{%0,%1,%2,%3}, {%4,%5,%6,%7}, {%8,%9}, {%0,%1,%2,%3};"
        : "+f"(c[0]), "+f"(c[1]), "+f"(c[2]), "+f"(c[3])
        : "r"(a[0]), "r"(a[1]), "r"(a[2]), "r"(a[3]), "r"(b0), "r"(b1));
}
__device__ __forceinline__ void cpa16(uint32_t sa, const void* g) {
    asm volatile("cp.async.cg.shared.global [%0], [%1], 16;" :: "r"(sa), "l"(g));
}

// ---------------- prep kernels ----------------
__global__ __launch_bounds__(256)
void prep_w2(const float* __restrict__ W, __half* __restrict__ hi, __half* __restrict__ lo)
{
    int i = blockIdx.x * blockDim.x + threadIdx.x;   // float4 index
    float4 v = ((const float4*)W)[i];
    __half hx = __float2half_rn(v.x), hy = __float2half_rn(v.y);
    __half hz = __float2half_rn(v.z), hw = __float2half_rn(v.w);
    __half lx = __float2half_rn(v.x - __half2float(hx));
    __half ly = __float2half_rn(v.y - __half2float(hy));
    __half lz = __float2half_rn(v.z - __half2float(hz));
    __half lw = __float2half_rn(v.w - __half2float(hw));
    ((uint2*)hi)[i] = make_uint2(packh2(hx, hy), packh2(hz, hw));
    ((uint2*)lo)[i] = make_uint2(packh2(lx, ly), packh2(lz, lw));
}

__global__ __launch_bounds__(256)
void prep_w1(const float* __restrict__ W, __half* __restrict__ O)
{
    int i = blockIdx.x * blockDim.x + threadIdx.x;
    float4 v = ((const float4*)W)[i];
    ((uint2*)O)[i] = make_uint2(packh2(__float2half_rn(v.x), __float2half_rn(v.y)),
                                packh2(__float2half_rn(v.z), __float2half_rn(v.w)));
}

__global__ __launch_bounds__(256)
void prep_bin(const float* __restrict__ X, __half* __restrict__ Y)
{
    int i = blockIdx.x * blockDim.x + threadIdx.x;
    float4 v = ((const float4*)X)[i];
    unsigned p0 = packh2(__float2half_rn(v.x >= 2.f ? 1.f : 0.f),
                         __float2half_rn(v.y >= 2.f ? 1.f : 0.f));
    unsigned p1 = packh2(__float2half_rn(v.z >= 2.f ? 1.f : 0.f),
                         __float2half_rn(v.w >= 2.f ? 1.f : 0.f));
    ((uint2*)Y)[i] = make_uint2(p0, p1);
}

// ---------------- fp16 HMMA GEMM ----------------
// TERMS=2: acc = A @ (W0 + W1)^T
// TERMS=1: acc = A @ W0^T ; optional MISHE: out = resid + mish(acc + bias)
template<int TERMS, bool MISHE, int S>
__global__ __launch_bounds__(256, (TERMS == 1) ? 2 : 1)
void hgemm(const __half* __restrict__ A,
           const __half* __restrict__ W0, const __half* __restrict__ W1,
           const float* __restrict__ bias, const float* __restrict__ resid,
           float* __restrict__ C)
{
    constexpr int NT = TERMS + 1;
    extern __shared__ char raw[];
    char* base = (char*)(((uintptr_t)raw + 1023) & ~(uintptr_t)1023);

    const int tid  = threadIdx.x;
    const int lane = tid & 31;
    const int wid  = tid >> 5;
    const int wm   = wid & 1;
    const int wn   = wid >> 1;
    const int bm   = blockIdx.y * 128;
    const int bn   = blockIdx.x * 128;

    float acc[4][4][4];
#pragma unroll
    for (int i = 0; i < 4; i++)
#pragma unroll
        for (int j = 0; j < 4; j++)
#pragma unroll
            for (int r = 0; r < 4; r++) acc[i][j][r] = 0.f;

    auto load = [&](int c) {
        char* st = base + (c % S) * NT * TILEB;
        const int k0 = c * BKC;
#pragma unroll
        for (int t = 0; t < NT; t++) {
            const __half* src = (t == 0) ? A : ((t == 1) ? W0 : W1);
            const int rb = (t == 0) ? bm : bn;
#pragma unroll
            for (int it = 0; it < 4; it++) {
                int id  = it * 256 + tid;
                int row = id >> 3;
                int ch  = id & 7;
                uint32_t sa = smem_u32(st + t * TILEB + SW128(row * 128 + ch * 16));
                cpa16(sa, src + (size_t)(rb + row) * D_ + k0 + ch * 8);
            }
        }
    };

    // prefetch S-1 chunks
#pragma unroll
    for (int p = 0; p < S - 1; p++) {
        load(p);
        asm volatile("cp.async.commit_group;" ::: "memory");
    }

    for (int c = 0; c < NCH; c++) {
        asm volatile("cp.async.wait_group %0;" :: "n"(S - 2) : "memory");
        __syncthreads();

        if (c + S - 1 < NCH) load(c + S - 1);
        asm volatile("cp.async.commit_group;" ::: "memory");

        const char* st  = base + (c % S) * NT * TILEB;
        const char* tA  = st;
        const char* tW0 = st + TILEB;
        const char* tW1 = st + 2 * TILEB;

        const int lr  = lane & 15;
        const int lc8 = (lane >> 4) * 8;

#pragma unroll
        for (int ks = 0; ks < 4; ks++) {
            const int cs2 = (ks * 16 + lc8) * 2;
            unsigned af[4][4];
#pragma unroll
            for (int mi = 0; mi < 4; mi++)
                ldm4(af[mi], tA + SW128((wm * 64 + mi * 16 + lr) * 128 + cs2));
            unsigned b0[2][4];
#pragma unroll
            for (int nb = 0; nb < 2; nb++)
                ldm4(b0[nb], tW0 + SW128((wn * 32 + nb * 16 + lr) * 128 + cs2));
            unsigned b1[2][4];
            if (TERMS == 2) {
#pragma unroll
                for (int nb = 0; nb < 2; nb++)
                    ldm4(b1[nb], tW1 + SW128((wn * 32 + nb * 16 + lr) * 128 + cs2));
            }
#pragma unroll
            for (int mi = 0; mi < 4; mi++) {
#pragma unroll
                for (int nj = 0; nj < 4; nj++) {
                    const int nb = nj >> 1, sl = nj & 1;
                    mma16816(acc[mi][nj], af[mi], b0[nb][sl], b0[nb][2 + sl]);
                    if (TERMS == 2)
                        mma16816(acc[mi][nj], af[mi], b1[nb][sl], b1[nb][2 + sl]);
                }
            }
        }
    }

    // epilogue
    const int g = lane >> 2, tg = lane & 3;
#pragma unroll
    for (int mi = 0; mi < 4; mi++) {
#pragma unroll
        for (int nj = 0; nj < 4; nj++) {
            int m0 = bm + wm * 64 + mi * 16 + g;
            int n0 = bn + wn * 32 + nj * 8 + tg * 2;
            float2 bs = *(const float2*)(bias + n0);
            float v0 = acc[mi][nj][0] + bs.x;
            float v1 = acc[mi][nj][1] + bs.y;
            float v2 = acc[mi][nj][2] + bs.x;
            float v3 = acc[mi][nj][3] + bs.y;
            if (MISHE) {
                float2 r0 = *(const float2*)(resid + (size_t)m0 * D_ + n0);
                float2 r1 = *(const float2*)(resid + (size_t)(m0 + 8) * D_ + n0);
                v0 = r0.x + mishf(v0);
                v1 = r0.y + mishf(v1);
                v2 = r1.x + mishf(v2);
                v3 = r1.y + mishf(v3);
            }
            *(float2*)(C + (size_t)m0 * D_ + n0)       = make_float2(v0, v1);
            *(float2*)(C + (size_t)(m0 + 8) * D_ + n0) = make_float2(v2, v3);
        }
    }
}

// ---------------- LayerNorm + LIF + bit-pack ----------------
__global__ __launch_bounds__(256)
void ln_lif_pack(const float* __restrict__ X,
                 const float* __restrict__ gamma, const float* __restrict__ beta,
                 unsigned* __restrict__ bits)
{
    const int row  = blockIdx.x;
    const int t    = threadIdx.x;
    const int lane = t & 31;
    const int wid  = t >> 5;

    const float* xr = X + (size_t)row * D_;

    float x[4];
    float s = 0.f, sq = 0.f;
#pragma unroll
    for (int i = 0; i < 4; i++) {
        x[i] = xr[i * 256 + t];
        s  += x[i];
        sq += x[i] * x[i];
    }
#pragma unroll
    for (int off = 16; off > 0; off >>= 1) {
        s  += __shfl_xor_sync(0xffffffffu, s,  off);
        sq += __shfl_xor_sync(0xffffffffu, sq, off);
    }
    __shared__ float ss[8], sqq[8];
    __shared__ float s_mu, s_rs;
    if (lane == 0) { ss[wid] = s; sqq[wid] = sq; }
    __syncthreads();
    if (wid == 0) {
        float a = (lane < 8) ? ss[lane]  : 0.f;
        float b = (lane < 8) ? sqq[lane] : 0.f;
#pragma unroll
        for (int off = 4; off > 0; off >>= 1) {
            a += __shfl_xor_sync(0xffffffffu, a, off);
            b += __shfl_xor_sync(0xffffffffu, b, off);
        }
        if (lane == 0) {
            float mu  = a * (1.f / D_);
            float var = b * (1.f / D_) - mu * mu;
            s_mu = mu;
            s_rs = rsqrtf(var + EPS_);
        }
    }
    __syncthreads();
    const float mu = s_mu, rs = s_rs;

#pragma unroll
    for (int i = 0; i < 4; i++) {
        int d = i * 256 + t;
        float y = (x[i] - mu) * rs * gamma[d] + beta[d];
        unsigned word = __ballot_sync(0xffffffffu, y >= 2.0f);
        if (lane == 0) bits[(size_t)row * 32 + i * 8 + wid] = word;
    }
}

// ---------------- flash attention: popcount QK + packed f32x2 PV ----------------
__global__ __launch_bounds__(128)
void attn_kernel(const unsigned* __restrict__ qbits, const unsigned* __restrict__ kbits,
                 const float* __restrict__ V, const float* __restrict__ mask,
                 float* __restrict__ out, __half* __restrict__ outh)
{
    const int qblk = blockIdx.x;
    const int h    = blockIdx.y;
    const int b    = blockIdx.z;
    const int t    = threadIdx.x;
    const int qr   = qblk * 128 + t;

    __shared__ float    sV[32][64];
    __shared__ float    sM[128][33];
    __shared__ unsigned sKb[32][2];

    const unsigned q0 = qbits[((size_t)(b * S_ + qr)) * 32 + h * 2 + 0];
    const unsigned q1 = qbits[((size_t)(b * S_ + qr)) * 32 + h * 2 + 1];

    unsigned long long acc2[32];
#pragma unroll
    for (int i = 0; i < 32; i++) acc2[i] = 0ull;
    float ssum = 0.f;

    const float* maskB = mask + (size_t)b * S_ * S_;

    for (int k0 = 0; k0 < S_; k0 += 32) {
        if (t < 64) {
            int j = t >> 1, w = t & 1;
            sKb[j][w] = kbits[((size_t)(b * S_ + k0 + j)) * 32 + h * 2 + w];
        }
        const float4* Vg = (const float4*)(V + ((size_t)(b * S_ + k0)) * D_ + h * HD_);
#pragma unroll
        for (int i = 0; i < 4; i++) {
            int id = t + 128 * i;
            int j  = id >> 4, d4 = id & 15;
            ((float4*)&sV[j][0])[d4] = Vg[(size_t)j * 256 + d4];
        }
#pragma unroll
        for (int i = 0; i < 32; i++) {
            int r = i * 4 + (t >> 5);
            int c = t & 31;
            sM[r][c] = maskB[(size_t)(qblk * 128 + r) * S_ + k0 + c];
        }
        __syncthreads();
#pragma unroll
        for (int j = 0; j < 32; j++) {
            int sc = __popc(q0 & sKb[j][0]) + __popc(q1 & sKb[j][1]);
            float e = __expf((float)sc * 0.125f * sM[t][j]);
            ssum += e;
            unsigned long long e2;
            asm("mov.b64 %0, {%1, %1};" : "=l"(e2) : "f"(e));
            const unsigned long long* vr = (const unsigned long long*)(&sV[j][0]);
#pragma unroll
            for (int d = 0; d < 32; d++) {
                asm("fma.rn.f32x2 %0, %1, %2, %0;"
                    : "+l"(acc2[d]) : "l"(e2), "l"(vr[d]));
            }
        }
        __syncthreads();
    }
    const float inv = 1.f / ssum;
    const size_t off = ((size_t)(b * S_ + qr)) * D_ + h * HD_;
    float2*   og = (float2*)(out + off);
    unsigned* oh = (unsigned*)(outh + off);
#pragma unroll
    for (int d = 0; d < 32; d++) {
        float lo, hi;
        asm("mov.b64 {%0, %1}, %2;" : "=f"(lo), "=f"(hi) : "l"(acc2[d]));
        float ox = lo * inv, oy = hi * inv;
        og[d] = make_float2(ox, oy);
        oh[d] = packh2(__float2half_rn(ox), __float2half_rn(oy));
    }
}

// ---------------- launch ----------------
extern "C" void kernel_launch(void* const* d_in, const int* in_sizes, int n_in,
                              void* d_out, int out_size)
{
    const float* Q   = (const float*)d_in[0];
    const float* K_  = (const float*)d_in[1];
    const float* adj = (const float*)d_in[2];
    const float* Wq  = (const float*)d_in[3];
    const float* bq  = (const float*)d_in[4];
    const float* Wk  = (const float*)d_in[5];
    const float* bk  = (const float*)d_in[6];
    const float* Wv  = (const float*)d_in[7];
    const float* bv  = (const float*)d_in[8];
    const float* Wo  = (const float*)d_in[9];
    const float* bo  = (const float*)d_in[10];
    const float* gq  = (const float*)d_in[11];
    const float* beq = (const float*)d_in[12];
    const float* gk  = (const float*)d_in[13];
    const float* bek = (const float*)d_in[14];
    float* out = (float*)d_out;

    float *Xq, *Xk, *Vb, *At;
    __half *Qb, *Kb, *Ath, *Wqh, *Wql, *Wkh, *Wkl, *Wv1, *Wo1;
    unsigned *qb, *kb;
    cudaGetSymbolAddress((void**)&Xq,  g_Xq);
    cudaGetSymbolAddress((void**)&Xk,  g_Xk);
    cudaGetSymbolAddress((void**)&Vb,  g_V);
    cudaGetSymbolAddress((void**)&At,  g_At);
    cudaGetSymbolAddress((void**)&Qb,  g_Qb);
    cudaGetSymbolAddress((void**)&Kb,  g_Kb);
    cudaGetSymbolAddress((void**)&Ath, g_Ath);
    cudaGetSymbolAddress((void**)&Wqh, g_Wqh);
    cudaGetSymbolAddress((void**)&Wql, g_Wql);
    cudaGetSymbolAddress((void**)&Wkh, g_Wkh);
    cudaGetSymbolAddress((void**)&Wkl, g_Wkl);
    cudaGetSymbolAddress((void**)&Wv1, g_Wv1);
    cudaGetSymbolAddress((void**)&Wo1, g_Wo1);
    cudaGetSymbolAddress((void**)&qb,  g_qb);
    cudaGetSymbolAddress((void**)&kb,  g_kb);

    const int smem2 = 4 * 3 * TILEB + 1024;   // 197632 (S=4, NT=3)
    const int smem1 = 3 * 2 * TILEB + 1024;   //  99328 (S=3, NT=2)
    cudaFuncSetAttribute((const void*)hgemm<2, false, 4>,
                         cudaFuncAttributeMaxDynamicSharedMemorySize, smem2);
    cudaFuncSetAttribute((const void*)hgemm<1, false, 3>,
                         cudaFuncAttributeMaxDynamicSharedMemorySize, smem1);
    cudaFuncSetAttribute((const void*)hgemm<1, true, 3>,
                         cudaFuncAttributeMaxDynamicSharedMemorySize, smem1);

    const int WELEM = D_ * D_;
    prep_w2<<<WELEM / 4 / 256, 256>>>(Wq, Wqh, Wql);
    prep_w2<<<WELEM / 4 / 256, 256>>>(Wk, Wkh, Wkl);
    prep_w1<<<WELEM / 4 / 256, 256>>>(Wv, Wv1);
    prep_w1<<<WELEM / 4 / 256, 256>>>(Wo, Wo1);
    prep_bin<<<ROWS * D_ / 4 / 256, 256>>>(Q,  Qb);
    prep_bin<<<ROWS * D_ / 4 / 256, 256>>>(K_, Kb);

    dim3 gg(D_ / 128, ROWS / 128);   // (8, 64)

    hgemm<2, false, 4><<<gg, 256, smem2>>>(Qb, Wqh, Wql, bq, nullptr, Xq);
    hgemm<2, false, 4><<<gg, 256, smem2>>>(Kb, Wkh, Wkl, bk, nullptr, Xk);
    hgemm<1, false, 3><<<gg, 256, smem1>>>(Kb, Wv1, nullptr, bv, nullptr, Vb);

    ln_lif_pack<<<ROWS, 256>>>(Xq, gq, beq, qb);
    ln_lif_pack<<<ROWS, 256>>>(Xk, gk, bek, kb);

    attn_kernel<<<dim3(8, H_, B_), 128>>>(qb, kb, Vb, adj, At, Ath);

    hgemm<1, true, 3><<<gg, 256, smem1>>>(Ath, Wo1, nullptr, bo, At, out);
}

// round 6
// speedup vs baseline: 3.9045x; 1.6704x over previous
#include <cuda_runtime.h>
#include <cuda_fp16.h>
#include <cstdint>

// Problem constants
#define B_   8
#define S_   1024
#define D_   1024
#define H_   16
#define HD_  64
#define ROWS (B_ * S_)
#define EPS_ 1e-5f

// GEMM tiling: CTA tile 128x128, K chunk 64 fp16 (= 128-byte SW128 rows)
#define BKC    64
#define TILEB  16384
#define NCH    (D_ / BKC)

#define SW128(x) ((x) ^ (((x) >> 3) & 0x70))

// ---------------- scratch (device globals) ----------------
__device__ float  g_Xq[ROWS * D_];
__device__ float  g_Xk[ROWS * D_];
__device__ float  g_At[ROWS * D_];
__device__ __half g_Qb[ROWS * D_];
__device__ __half g_Kb[ROWS * D_];
__device__ __half g_Ath[ROWS * D_];
__device__ __half g_Vh[ROWS * D_];
__device__ __half g_Vl[ROWS * D_];
__device__ __half g_Wqh[D_ * D_];
__device__ __half g_Wql[D_ * D_];
__device__ __half g_Wkh[D_ * D_];
__device__ __half g_Wkl[D_ * D_];
__device__ __half g_Wv1[D_ * D_];
__device__ __half g_Wo1[D_ * D_];
__device__ unsigned g_qb[ROWS * 32];
__device__ unsigned g_kb[ROWS * 32];

// ---------------- helpers ----------------
__device__ __forceinline__ uint32_t smem_u32(const void* p) {
    return (uint32_t)__cvta_generic_to_shared(p);
}
__device__ __forceinline__ float mishf(float x) {
    float sp = (x > 20.f) ? x : log1pf(__expf(x));
    return x * tanhf(sp);
}
__device__ __forceinline__ unsigned packh2(__half a, __half b) {
    __half2 t = __halves2half2(a, b);
    return *reinterpret_cast<unsigned*>(&t);
}
__device__ __forceinline__ void ldm4(unsigned* r, const void* p) {
    unsigned addr = smem_u32(p);
    asm volatile("ldmatrix.sync.aligned.m8n8.x4.shared.b16 {%0,%1,%2,%3}, [%4];"
        : "=r"(r[0]), "=r"(r[1]), "=r"(r[2]), "=r"(r[3]) : "r"(addr));
}
__device__ __forceinline__ void ldm4t(unsigned* r, const void* p) {
    unsigned addr = smem_u32(p);
    asm volatile("ldmatrix.sync.aligned.m8n8.x4.trans.shared.b16 {%0,%1,%2,%3}, [%4];"
        : "=r"(r[0]), "=r"(r[1]), "=r"(r[2]), "=r"(r[3]) : "r"(addr));
}
__device__ __forceinline__ void mma16816(float* c, const unsigned* a, unsigned b0, unsigned b1) {
    asm volatile("mma.sync.aligned.m16n8k16.row.col.f32.f16.f16.f32 "
        "{%0,%1,%2,%3}, {%4,%5,%6,%7}, {%8,%9}, {%0,%1,%2,%3};"
        : "+f"(c[0]), "+f"(c[1]), "+f"(c[2]), "+f"(c[3])
        : "r"(a[0]), "r"(a[1]), "r"(a[2]), "r"(a[3]), "r"(b0), "r"(b1));
}
__device__ __forceinline__ void cpa16(uint32_t sa, const void* g) {
    asm volatile("cp.async.cg.shared.global [%0], [%1], 16;" :: "r"(sa), "l"(g));
}

// ---------------- prep kernels ----------------
__global__ __launch_bounds__(256)
void prep_w2(const float* __restrict__ W, __half* __restrict__ hi, __half* __restrict__ lo)
{
    int i = blockIdx.x * blockDim.x + threadIdx.x;
    float4 v = ((const float4*)W)[i];
    __half hx = __float2half_rn(v.x), hy = __float2half_rn(v.y);
    __half hz = __float2half_rn(v.z), hw = __float2half_rn(v.w);
    ((uint2*)hi)[i] = make_uint2(packh2(hx, hy), packh2(hz, hw));
    ((uint2*)lo)[i] = make_uint2(
        packh2(__float2half_rn(v.x - __half2float(hx)), __float2half_rn(v.y - __half2float(hy))),
        packh2(__float2half_rn(v.z - __half2float(hz)), __float2half_rn(v.w - __half2float(hw))));
}

__global__ __launch_bounds__(256)
void prep_w1(const float* __restrict__ W, __half* __restrict__ O)
{
    int i = blockIdx.x * blockDim.x + threadIdx.x;
    float4 v = ((const float4*)W)[i];
    ((uint2*)O)[i] = make_uint2(packh2(__float2half_rn(v.x), __float2half_rn(v.y)),
                                packh2(__float2half_rn(v.z), __float2half_rn(v.w)));
}

__global__ __launch_bounds__(256)
void prep_bin(const float* __restrict__ X, __half* __restrict__ Y)
{
    int i = blockIdx.x * blockDim.x + threadIdx.x;
    float4 v = ((const float4*)X)[i];
    ((uint2*)Y)[i] = make_uint2(
        packh2(__float2half_rn(v.x >= 2.f ? 1.f : 0.f), __float2half_rn(v.y >= 2.f ? 1.f : 0.f)),
        packh2(__float2half_rn(v.z >= 2.f ? 1.f : 0.f), __float2half_rn(v.w >= 2.f ? 1.f : 0.f)));
}

// ---------------- fp16 HMMA GEMM ----------------
// TERMS=2: acc = A @ (W0 + W1)^T
// TERMS=1: acc = A @ W0^T
// MISHE : out = resid + mish(acc + bias)
// HOUT  : emit fp16 hi/lo split of (acc + bias) instead of fp32 C
template<int TERMS, bool MISHE, bool HOUT, int S>
__global__ __launch_bounds__(256, (TERMS == 1) ? 2 : 1)
void hgemm(const __half* __restrict__ A,
           const __half* __restrict__ W0, const __half* __restrict__ W1,
           const float* __restrict__ bias, const float* __restrict__ resid,
           float* __restrict__ C, __half* __restrict__ Oh, __half* __restrict__ Ol)
{
    constexpr int NT = TERMS + 1;
    extern __shared__ char raw[];
    char* base = (char*)(((uintptr_t)raw + 1023) & ~(uintptr_t)1023);

    const int tid  = threadIdx.x;
    const int lane = tid & 31;
    const int wid  = tid >> 5;
    const int wm   = wid & 1;
    const int wn   = wid >> 1;
    const int bm   = blockIdx.y * 128;
    const int bn   = blockIdx.x * 128;

    float acc[4][4][4];
#pragma unroll
    for (int i = 0; i < 4; i++)
#pragma unroll
        for (int j = 0; j < 4; j++)
#pragma unroll
            for (int r = 0; r < 4; r++) acc[i][j][r] = 0.f;

    auto load = [&](int c) {
        char* st = base + (c % S) * NT * TILEB;
        const int k0 = c * BKC;
#pragma unroll
        for (int t = 0; t < NT; t++) {
            const __half* src = (t == 0) ? A : ((t == 1) ? W0 : W1);
            const int rb = (t == 0) ? bm : bn;
#pragma unroll
            for (int it = 0; it < 4; it++) {
                int id  = it * 256 + tid;
                int row = id >> 3;
                int ch  = id & 7;
                uint32_t sa = smem_u32(st + t * TILEB + SW128(row * 128 + ch * 16));
                cpa16(sa, src + (size_t)(rb + row) * D_ + k0 + ch * 8);
            }
        }
    };

#pragma unroll
    for (int p = 0; p < S - 1; p++) {
        load(p);
        asm volatile("cp.async.commit_group;" ::: "memory");
    }

    for (int c = 0; c < NCH; c++) {
        asm volatile("cp.async.wait_group %0;" :: "n"(S - 2) : "memory");
        __syncthreads();

        if (c + S - 1 < NCH) load(c + S - 1);
        asm volatile("cp.async.commit_group;" ::: "memory");

        const char* st  = base + (c % S) * NT * TILEB;
        const char* tA  = st;
        const char* tW0 = st + TILEB;
        const char* tW1 = st + 2 * TILEB;

        const int lr  = lane & 15;
        const int lc8 = (lane >> 4) * 8;

#pragma unroll
        for (int ks = 0; ks < 4; ks++) {
            const int cs2 = (ks * 16 + lc8) * 2;
            unsigned af[4][4];
#pragma unroll
            for (int mi = 0; mi < 4; mi++)
                ldm4(af[mi], tA + SW128((wm * 64 + mi * 16 + lr) * 128 + cs2));
            unsigned b0[2][4];
#pragma unroll
            for (int nb = 0; nb < 2; nb++)
                ldm4(b0[nb], tW0 + SW128((wn * 32 + nb * 16 + lr) * 128 + cs2));
            unsigned b1[2][4];
            if (TERMS == 2) {
#pragma unroll
                for (int nb = 0; nb < 2; nb++)
                    ldm4(b1[nb], tW1 + SW128((wn * 32 + nb * 16 + lr) * 128 + cs2));
            }
#pragma unroll
            for (int mi = 0; mi < 4; mi++) {
#pragma unroll
                for (int nj = 0; nj < 4; nj++) {
                    const int nb = nj >> 1, sl = nj & 1;
                    mma16816(acc[mi][nj], af[mi], b0[nb][sl], b0[nb][2 + sl]);
                    if (TERMS == 2)
                        mma16816(acc[mi][nj], af[mi], b1[nb][sl], b1[nb][2 + sl]);
                }
            }
        }
    }

    // epilogue
    const int g = lane >> 2, tg = lane & 3;
#pragma unroll
    for (int mi = 0; mi < 4; mi++) {
#pragma unroll
        for (int nj = 0; nj < 4; nj++) {
            int m0 = bm + wm * 64 + mi * 16 + g;
            int n0 = bn + wn * 32 + nj * 8 + tg * 2;
            float2 bs = *(const float2*)(bias + n0);
            float v0 = acc[mi][nj][0] + bs.x;
            float v1 = acc[mi][nj][1] + bs.y;
            float v2 = acc[mi][nj][2] + bs.x;
            float v3 = acc[mi][nj][3] + bs.y;
            if (MISHE) {
                float2 r0 = *(const float2*)(resid + (size_t)m0 * D_ + n0);
                float2 r1 = *(const float2*)(resid + (size_t)(m0 + 8) * D_ + n0);
                v0 = r0.x + mishf(v0);
                v1 = r0.y + mishf(v1);
                v2 = r1.x + mishf(v2);
                v3 = r1.y + mishf(v3);
            }
            if (HOUT) {
                __half h0 = __float2half_rn(v0), h1 = __float2half_rn(v1);
                __half h2 = __float2half_rn(v2), h3 = __float2half_rn(v3);
                *(unsigned*)(Oh + (size_t)m0 * D_ + n0)       = packh2(h0, h1);
                *(unsigned*)(Oh + (size_t)(m0 + 8) * D_ + n0) = packh2(h2, h3);
                *(unsigned*)(Ol + (size_t)m0 * D_ + n0) =
                    packh2(__float2half_rn(v0 - __half2float(h0)),
                           __float2half_rn(v1 - __half2float(h1)));
                *(unsigned*)(Ol + (size_t)(m0 + 8) * D_ + n0) =
                    packh2(__float2half_rn(v2 - __half2float(h2)),
                           __float2half_rn(v3 - __half2float(h3)));
            } else {
                *(float2*)(C + (size_t)m0 * D_ + n0)       = make_float2(v0, v1);
                *(float2*)(C + (size_t)(m0 + 8) * D_ + n0) = make_float2(v2, v3);
            }
        }
    }
}

// ---------------- LayerNorm + LIF + bit-pack ----------------
__global__ __launch_bounds__(256)
void ln_lif_pack(const float* __restrict__ X,
                 const float* __restrict__ gamma, const float* __restrict__ beta,
                 unsigned* __restrict__ bits)
{
    const int row  = blockIdx.x;
    const int t    = threadIdx.x;
    const int lane = t & 31;
    const int wid  = t >> 5;

    const float* xr = X + (size_t)row * D_;

    float x[4];
    float s = 0.f, sq = 0.f;
#pragma unroll
    for (int i = 0; i < 4; i++) {
        x[i] = xr[i * 256 + t];
        s  += x[i];
        sq += x[i] * x[i];
    }
#pragma unroll
    for (int off = 16; off > 0; off >>= 1) {
        s  += __shfl_xor_sync(0xffffffffu, s,  off);
        sq += __shfl_xor_sync(0xffffffffu, sq, off);
    }
    __shared__ float ss[8], sqq[8];
    __shared__ float s_mu, s_rs;
    if (lane == 0) { ss[wid] = s; sqq[wid] = sq; }
    __syncthreads();
    if (wid == 0) {
        float a = (lane < 8) ? ss[lane]  : 0.f;
        float b = (lane < 8) ? sqq[lane] : 0.f;
#pragma unroll
        for (int off = 4; off > 0; off >>= 1) {
            a += __shfl_xor_sync(0xffffffffu, a, off);
            b += __shfl_xor_sync(0xffffffffu, b, off);
        }
        if (lane == 0) {
            float mu  = a * (1.f / D_);
            float var = b * (1.f / D_) - mu * mu;
            s_mu = mu;
            s_rs = rsqrtf(var + EPS_);
        }
    }
    __syncthreads();
    const float mu = s_mu, rs = s_rs;

#pragma unroll
    for (int i = 0; i < 4; i++) {
        int d = i * 256 + t;
        float y = (x[i] - mu) * rs * gamma[d] + beta[d];
        unsigned word = __ballot_sync(0xffffffffu, y >= 2.0f);
        if (lane == 0) bits[(size_t)row * 32 + i * 8 + wid] = word;
    }
}

// ---------------- HMMA flash attention ----------------
// smem layout (bytes from aligned base):
#define AT_SM   0                       // float [128][33]      16896
#define AT_PH   16896                   // half  [128][40]      10240
#define AT_PL   27136                   // half  [128][40]      10240
#define AT_VH   37376                   // half  [2][32][72]     9216
#define AT_VL   46592                   // half  [2][32][72]     9216
#define AT_KB   55808                   // unsigned [32][2]       256
#define AT_SUM  56064                   // float [128]            512
#define AT_SMEM (56576 + 1024)

__global__ __launch_bounds__(128, 3)
void attn_kernel(const unsigned* __restrict__ qbits, const unsigned* __restrict__ kbits,
                 const __half* __restrict__ Vh, const __half* __restrict__ Vl,
                 const float* __restrict__ mask,
                 float* __restrict__ out, __half* __restrict__ outh)
{
    extern __shared__ char raw[];
    char* sb = (char*)(((uintptr_t)raw + 1023) & ~(uintptr_t)1023);
    float*    sM   = (float*)(sb + AT_SM);     // stride 33
    __half*   sPh  = (__half*)(sb + AT_PH);    // stride 40
    __half*   sPl  = (__half*)(sb + AT_PL);
    __half*   sVh  = (__half*)(sb + AT_VH);    // [buf][32][72]
    __half*   sVl  = (__half*)(sb + AT_VL);
    unsigned* sKb  = (unsigned*)(sb + AT_KB);
    float*    sSum = (float*)(sb + AT_SUM);

    const int qblk = blockIdx.x;
    const int h    = blockIdx.y;
    const int b    = blockIdx.z;
    const int t    = threadIdx.x;
    const int lane = t & 31;
    const int wid  = t >> 5;

    const unsigned q0 = qbits[((size_t)(b * S_ + qblk * 128 + t)) * 32 + h * 2 + 0];
    const unsigned q1 = qbits[((size_t)(b * S_ + qblk * 128 + t)) * 32 + h * 2 + 1];

    float acc[2][8][4];
#pragma unroll
    for (int i = 0; i < 2; i++)
#pragma unroll
        for (int j = 0; j < 8; j++)
#pragma unroll
            for (int r = 0; r < 4; r++) acc[i][j][r] = 0.f;
    float ssum = 0.f;

    const float* maskB = mask + (size_t)b * S_ * S_ + (size_t)(qblk * 128) * S_;

    auto loadV = [&](int c) {
        __half* dvh = sVh + (c & 1) * 32 * 72;
        __half* dvl = sVl + (c & 1) * 32 * 72;
        const size_t gb = ((size_t)(b * S_ + c * 32)) * D_ + h * HD_;
#pragma unroll
        for (int i = 0; i < 2; i++) {
            int id = i * 128 + t;          // 0..255
            int r  = id >> 3, ch = id & 7; // 32 rows x 8 chunks
            cpa16(smem_u32(dvh + r * 72 + ch * 8), Vh + gb + (size_t)r * D_ + ch * 8);
            cpa16(smem_u32(dvl + r * 72 + ch * 8), Vl + gb + (size_t)r * D_ + ch * 8);
        }
    };

    loadV(0);
    asm volatile("cp.async.commit_group;" ::: "memory");

    for (int c = 0; c < 32; c++) {
        const int k0 = c * 32;
        // mask tile -> sM (LDG.128 coalesced, STS stride-33)
#pragma unroll
        for (int i = 0; i < 8; i++) {
            int id  = i * 128 + t;
            int r   = id >> 3, c4 = (id & 7) * 4;
            float4 m4 = *(const float4*)(maskB + (size_t)r * S_ + k0 + c4);
            float* dst = sM + r * 33 + c4;
            dst[0] = m4.x; dst[1] = m4.y; dst[2] = m4.z; dst[3] = m4.w;
        }
        if (t < 64) {
            int j = t >> 1, w = t & 1;
            sKb[j * 2 + w] = kbits[((size_t)(b * S_ + k0 + j)) * 32 + h * 2 + w];
        }
        __syncthreads();   // sM/sKb visible; prior MMA phase done (sP reusable)

        // issue next V tile
        if (c + 1 < 32) loadV(c + 1);
        asm volatile("cp.async.commit_group;" ::: "memory");

        // e-compute: thread t owns q-row t
        {
            const float* mr = sM + t * 33;
            __half* ph = sPh + t * 40;
            __half* pl = sPl + t * 40;
#pragma unroll
            for (int j = 0; j < 32; j += 2) {
                int   s0 = __popc(q0 & sKb[j * 2]) + __popc(q1 & sKb[j * 2 + 1]);
                int   s1 = __popc(q0 & sKb[j * 2 + 2]) + __popc(q1 & sKb[j * 2 + 3]);
                float e0 = __expf((float)s0 * 0.125f * mr[j]);
                float e1 = __expf((float)s1 * 0.125f * mr[j + 1]);
                ssum += e0 + e1;
                __half h0 = __float2half_rn(e0), h1 = __float2half_rn(e1);
                *(unsigned*)(ph + j) = packh2(h0, h1);
                *(unsigned*)(pl + j) = packh2(__float2half_rn(e0 - __half2float(h0)),
                                              __float2half_rn(e1 - __half2float(h1)));
            }
        }
        __syncthreads();   // sP visible
        asm volatile("cp.async.wait_group 1;" ::: "memory");  // V(c) ready

        // MMA phase: P[128x32] @ V[32x64], 3 terms
        const __half* vhb = sVh + (c & 1) * 32 * 72;
        const __half* vlb = sVl + (c & 1) * 32 * 72;
        const int lr  = lane & 15;
        const int lc8 = (lane >> 4) * 8;
        const int l8  = lane & 7;
        const int ks8 = ((lane >> 3) & 1) * 8;
        const int ns8 = (lane >> 4) * 8;
#pragma unroll
        for (int kk = 0; kk < 2; kk++) {
            unsigned ah[2][4], al[2][4];
#pragma unroll
            for (int mi = 0; mi < 2; mi++) {
                const int rofs = (wid * 32 + mi * 16 + lr) * 40 + kk * 16 + lc8;
                ldm4(ah[mi], sPh + rofs);
                ldm4(al[mi], sPl + rofs);
            }
            unsigned vh[4][4], vl[4][4];
#pragma unroll
            for (int nb = 0; nb < 4; nb++) {
                const int vofs = (kk * 16 + ks8 + l8) * 72 + nb * 16 + ns8;
                ldm4t(vh[nb], vhb + vofs);
                ldm4t(vl[nb], vlb + vofs);
            }
#pragma unroll
            for (int mi = 0; mi < 2; mi++) {
#pragma unroll
                for (int nj = 0; nj < 8; nj++) {
                    const int nb = nj >> 1, half = nj & 1;
                    mma16816(acc[mi][nj], ah[mi], vh[nb][half * 2], vh[nb][half * 2 + 1]);
                    mma16816(acc[mi][nj], al[mi], vh[nb][half * 2], vh[nb][half * 2 + 1]);
                    mma16816(acc[mi][nj], ah[mi], vl[nb][half * 2], vl[nb][half * 2 + 1]);
                }
            }
        }
    }

    sSum[t] = ssum;
    __syncthreads();

    // epilogue
    const int g = lane >> 2, tg = lane & 3;
#pragma unroll
    for (int mi = 0; mi < 2; mi++) {
        const int qr0 = wid * 32 + mi * 16 + g;
        const float inv0 = 1.f / sSum[qr0];
        const float inv1 = 1.f / sSum[qr0 + 8];
        const size_t base0 = ((size_t)(b * S_ + qblk * 128 + qr0)) * D_ + h * HD_;
#pragma unroll
        for (int nj = 0; nj < 8; nj++) {
            const int n = nj * 8 + tg * 2;
            float v0 = acc[mi][nj][0] * inv0;
            float v1 = acc[mi][nj][1] * inv0;
            float v2 = acc[mi][nj][2] * inv1;
            float v3 = acc[mi][nj][3] * inv1;
            *(float2*)(out + base0 + n)           = make_float2(v0, v1);
            *(float2*)(out + base0 + 8 * D_ + n)  = make_float2(v2, v3);
            *(unsigned*)(outh + base0 + n)          = packh2(__float2half_rn(v0), __float2half_rn(v1));
            *(unsigned*)(outh + base0 + 8 * D_ + n) = packh2(__float2half_rn(v2), __float2half_rn(v3));
        }
    }
}

// ---------------- launch ----------------
extern "C" void kernel_launch(void* const* d_in, const int* in_sizes, int n_in,
                              void* d_out, int out_size)
{
    const float* Q   = (const float*)d_in[0];
    const float* K_  = (const float*)d_in[1];
    const float* adj = (const float*)d_in[2];
    const float* Wq  = (const float*)d_in[3];
    const float* bq  = (const float*)d_in[4];
    const float* Wk  = (const float*)d_in[5];
    const float* bk  = (const float*)d_in[6];
    const float* Wv  = (const float*)d_in[7];
    const float* bv  = (const float*)d_in[8];
    const float* Wo  = (const float*)d_in[9];
    const float* bo  = (const float*)d_in[10];
    const float* gq  = (const float*)d_in[11];
    const float* beq = (const float*)d_in[12];
    const float* gk  = (const float*)d_in[13];
    const float* bek = (const float*)d_in[14];
    float* out = (float*)d_out;

    float *Xq, *Xk, *At;
    __half *Qb, *Kb, *Ath, *Vh, *Vl, *Wqh, *Wql, *Wkh, *Wkl, *Wv1, *Wo1;
    unsigned *qb, *kb;
    cudaGetSymbolAddress((void**)&Xq,  g_Xq);
    cudaGetSymbolAddress((void**)&Xk,  g_Xk);
    cudaGetSymbolAddress((void**)&At,  g_At);
    cudaGetSymbolAddress((void**)&Qb,  g_Qb);
    cudaGetSymbolAddress((void**)&Kb,  g_Kb);
    cudaGetSymbolAddress((void**)&Ath, g_Ath);
    cudaGetSymbolAddress((void**)&Vh,  g_Vh);
    cudaGetSymbolAddress((void**)&Vl,  g_Vl);
    cudaGetSymbolAddress((void**)&Wqh, g_Wqh);
    cudaGetSymbolAddress((void**)&Wql, g_Wql);
    cudaGetSymbolAddress((void**)&Wkh, g_Wkh);
    cudaGetSymbolAddress((void**)&Wkl, g_Wkl);
    cudaGetSymbolAddress((void**)&Wv1, g_Wv1);
    cudaGetSymbolAddress((void**)&Wo1, g_Wo1);
    cudaGetSymbolAddress((void**)&qb,  g_qb);
    cudaGetSymbolAddress((void**)&kb,  g_kb);

    const int smem2 = 4 * 3 * TILEB + 1024;
    const int smem1 = 3 * 2 * TILEB + 1024;
    cudaFuncSetAttribute((const void*)hgemm<2, false, false, 4>,
                         cudaFuncAttributeMaxDynamicSharedMemorySize, smem2);
    cudaFuncSetAttribute((const void*)hgemm<1, false, true, 3>,
                         cudaFuncAttributeMaxDynamicSharedMemorySize, smem1);
    cudaFuncSetAttribute((const void*)hgemm<1, true, false, 3>,
                         cudaFuncAttributeMaxDynamicSharedMemorySize, smem1);
    cudaFuncSetAttribute((const void*)attn_kernel,
                         cudaFuncAttributeMaxDynamicSharedMemorySize, AT_SMEM);

    const int WELEM = D_ * D_;
    prep_w2<<<WELEM / 4 / 256, 256>>>(Wq, Wqh, Wql);
    prep_w2<<<WELEM / 4 / 256, 256>>>(Wk, Wkh, Wkl);
    prep_w1<<<WELEM / 4 / 256, 256>>>(Wv, Wv1);
    prep_w1<<<WELEM / 4 / 256, 256>>>(Wo, Wo1);
    prep_bin<<<ROWS * D_ / 4 / 256, 256>>>(Q,  Qb);
    prep_bin<<<ROWS * D_ / 4 / 256, 256>>>(K_, Kb);

    dim3 gg(D_ / 128, ROWS / 128);

    hgemm<2, false, false, 4><<<gg, 256, smem2>>>(Qb, Wqh, Wql, bq, nullptr, Xq, nullptr, nullptr);
    hgemm<2, false, false, 4><<<gg, 256, smem2>>>(Kb, Wkh, Wkl, bk, nullptr, Xk, nullptr, nullptr);
    hgemm<1, false, true, 3><<<gg, 256, smem1>>>(Kb, Wv1, nullptr, bv, nullptr, nullptr, Vh, Vl);

    ln_lif_pack<<<ROWS, 256>>>(Xq, gq, beq, qb);
    ln_lif_pack<<<ROWS, 256>>>(Xk, gk, bek, kb);

    attn_kernel<<<dim3(8, H_, B_), 128, AT_SMEM>>>(qb, kb, Vh, Vl, adj, At, Ath);

    hgemm<1, true, false, 3><<<gg, 256, smem1>>>(Ath, Wo1, nullptr, bo, At, out, nullptr, nullptr);
}

// round 7
// speedup vs baseline: 4.1889x; 1.0728x over previous
#include <cuda_runtime.h>
#include <cuda_fp16.h>
#include <cstdint>

// Problem constants
#define B_   8
#define S_   1024
#define D_   1024
#define H_   16
#define HD_  64
#define ROWS (B_ * S_)
#define EPS_ 1e-5f

// GEMM tiling: CTA tile 128x128, K chunk 64 fp16 (= 128-byte SW128 rows)
#define BKC    64
#define TILEB  16384
#define NCH    (D_ / BKC)

#define SW128(x) ((x) ^ (((x) >> 3) & 0x70))

// ---------------- scratch (device globals) ----------------
__device__ float  g_Xq[ROWS * D_];
__device__ float  g_Xk[ROWS * D_];
__device__ float  g_At[ROWS * D_];
__device__ __half g_Qb[ROWS * D_];
__device__ __half g_Kb[ROWS * D_];
__device__ __half g_Ath[ROWS * D_];
__device__ __half g_Vh[ROWS * D_];
__device__ __half g_Vl[ROWS * D_];
__device__ __half g_Wqh[D_ * D_];
__device__ __half g_Wql[D_ * D_];
__device__ __half g_Wkh[D_ * D_];
__device__ __half g_Wkl[D_ * D_];
__device__ __half g_Wv1[D_ * D_];
__device__ __half g_Wo1[D_ * D_];
__device__ unsigned g_qb[ROWS * 32];
__device__ unsigned g_kb[ROWS * 32];
__device__ unsigned g_mb[B_ * 32 * S_];   // mask bits: [b][kchunk][q]

// ---------------- helpers ----------------
__device__ __forceinline__ uint32_t smem_u32(const void* p) {
    return (uint32_t)__cvta_generic_to_shared(p);
}
__device__ __forceinline__ float mishf(float x) {
    float sp = (x > 20.f) ? x : log1pf(__expf(x));
    return x * tanhf(sp);
}
__device__ __forceinline__ unsigned packh2(__half a, __half b) {
    __half2 t = __halves2half2(a, b);
    return *reinterpret_cast<unsigned*>(&t);
}
__device__ __forceinline__ void ldm4(unsigned* r, const void* p) {
    unsigned addr = smem_u32(p);
    asm volatile("ldmatrix.sync.aligned.m8n8.x4.shared.b16 {%0,%1,%2,%3}, [%4];"
        : "=r"(r[0]), "=r"(r[1]), "=r"(r[2]), "=r"(r[3]) : "r"(addr));
}
__device__ __forceinline__ void ldm4t(unsigned* r, const void* p) {
    unsigned addr = smem_u32(p);
    asm volatile("ldmatrix.sync.aligned.m8n8.x4.trans.shared.b16 {%0,%1,%2,%3}, [%4];"
        : "=r"(r[0]), "=r"(r[1]), "=r"(r[2]), "=r"(r[3]) : "r"(addr));
}
__device__ __forceinline__ void mma16816(float* c, const unsigned* a, unsigned b0, unsigned b1) {
    asm volatile("mma.sync.aligned.m16n8k16.row.col.f32.f16.f16.f32 "
        "{%0,%1,%2,%3}, {%4,%5,%6,%7}, {%8,%9}, {%0,%1,%2,%3};"
        : "+f"(c[0]), "+f"(c[1]), "+f"(c[2]), "+f"(c[3])
        : "r"(a[0]), "r"(a[1]), "r"(a[2]), "r"(a[3]), "r"(b0), "r"(b1));
}
__device__ __forceinline__ void cpa16(uint32_t sa, const void* g) {
    asm volatile("cp.async.cg.shared.global [%0], [%1], 16;" :: "r"(sa), "l"(g));
}

// ---------------- prep kernels ----------------
__global__ __launch_bounds__(256)
void prep_w2(const float* __restrict__ W, __half* __restrict__ hi, __half* __restrict__ lo)
{
    int i = blockIdx.x * blockDim.x + threadIdx.x;
    float4 v = ((const float4*)W)[i];
    __half hx = __float2half_rn(v.x), hy = __float2half_rn(v.y);
    __half hz = __float2half_rn(v.z), hw = __float2half_rn(v.w);
    ((uint2*)hi)[i] = make_uint2(packh2(hx, hy), packh2(hz, hw));
    ((uint2*)lo)[i] = make_uint2(
        packh2(__float2half_rn(v.x - __half2float(hx)), __float2half_rn(v.y - __half2float(hy))),
        packh2(__float2half_rn(v.z - __half2float(hz)), __float2half_rn(v.w - __half2float(hw))));
}

__global__ __launch_bounds__(256)
void prep_w1(const float* __restrict__ W, __half* __restrict__ O)
{
    int i = blockIdx.x * blockDim.x + threadIdx.x;
    float4 v = ((const float4*)W)[i];
    ((uint2*)O)[i] = make_uint2(packh2(__float2half_rn(v.x), __float2half_rn(v.y)),
                                packh2(__float2half_rn(v.z), __float2half_rn(v.w)));
}

__global__ __launch_bounds__(256)
void prep_bin(const float* __restrict__ X, __half* __restrict__ Y)
{
    int i = blockIdx.x * blockDim.x + threadIdx.x;
    float4 v = ((const float4*)X)[i];
    ((uint2*)Y)[i] = make_uint2(
        packh2(__float2half_rn(v.x >= 2.f ? 1.f : 0.f), __float2half_rn(v.y >= 2.f ? 1.f : 0.f)),
        packh2(__float2half_rn(v.z >= 2.f ? 1.f : 0.f), __float2half_rn(v.w >= 2.f ? 1.f : 0.f)));
}

// mask [b][q][k] fp32 -> bits word[b][c][q], bit j = (mask[b][q][c*32+j] != 0)
__global__ __launch_bounds__(256)
void prep_mask(const float* __restrict__ M, unsigned* __restrict__ mb)
{
    int w = blockIdx.x * blockDim.x + threadIdx.x;   // 0 .. B*32*1024-1
    int b = w >> 15;
    int c = (w >> 10) & 31;
    int q = w & 1023;
    const float4* src = (const float4*)(M + ((size_t)(b * S_ + q)) * S_ + c * 32);
    unsigned word = 0;
#pragma unroll
    for (int i = 0; i < 8; i++) {
        float4 m4 = src[i];
        word |= (m4.x != 0.f ? 1u : 0u) << (i * 4 + 0);
        word |= (m4.y != 0.f ? 1u : 0u) << (i * 4 + 1);
        word |= (m4.z != 0.f ? 1u : 0u) << (i * 4 + 2);
        word |= (m4.w != 0.f ? 1u : 0u) << (i * 4 + 3);
    }
    mb[w] = word;
}

// ---------------- fp16 HMMA GEMM ----------------
template<int TERMS, bool MISHE, bool HOUT, int S>
__global__ __launch_bounds__(256, (TERMS == 1) ? 2 : 1)
void hgemm(const __half* __restrict__ A,
           const __half* __restrict__ W0, const __half* __restrict__ W1,
           const float* __restrict__ bias, const float* __restrict__ resid,
           float* __restrict__ C, __half* __restrict__ Oh, __half* __restrict__ Ol)
{
    constexpr int NT = TERMS + 1;
    extern __shared__ char raw[];
    char* base = (char*)(((uintptr_t)raw + 1023) & ~(uintptr_t)1023);

    const int tid  = threadIdx.x;
    const int lane = tid & 31;
    const int wid  = tid >> 5;
    const int wm   = wid & 1;
    const int wn   = wid >> 1;
    const int bm   = blockIdx.y * 128;
    const int bn   = blockIdx.x * 128;

    float acc[4][4][4];
#pragma unroll
    for (int i = 0; i < 4; i++)
#pragma unroll
        for (int j = 0; j < 4; j++)
#pragma unroll
            for (int r = 0; r < 4; r++) acc[i][j][r] = 0.f;

    auto load = [&](int c) {
        char* st = base + (c % S) * NT * TILEB;
        const int k0 = c * BKC;
#pragma unroll
        for (int t = 0; t < NT; t++) {
            const __half* src = (t == 0) ? A : ((t == 1) ? W0 : W1);
            const int rb = (t == 0) ? bm : bn;
#pragma unroll
            for (int it = 0; it < 4; it++) {
                int id  = it * 256 + tid;
                int row = id >> 3;
                int ch  = id & 7;
                uint32_t sa = smem_u32(st + t * TILEB + SW128(row * 128 + ch * 16));
                cpa16(sa, src + (size_t)(rb + row) * D_ + k0 + ch * 8);
            }
        }
    };

#pragma unroll
    for (int p = 0; p < S - 1; p++) {
        load(p);
        asm volatile("cp.async.commit_group;" ::: "memory");
    }

    for (int c = 0; c < NCH; c++) {
        asm volatile("cp.async.wait_group %0;" :: "n"(S - 2) : "memory");
        __syncthreads();

        if (c + S - 1 < NCH) load(c + S - 1);
        asm volatile("cp.async.commit_group;" ::: "memory");

        const char* st  = base + (c % S) * NT * TILEB;
        const char* tA  = st;
        const char* tW0 = st + TILEB;
        const char* tW1 = st + 2 * TILEB;

        const int lr  = lane & 15;
        const int lc8 = (lane >> 4) * 8;

#pragma unroll
        for (int ks = 0; ks < 4; ks++) {
            const int cs2 = (ks * 16 + lc8) * 2;
            unsigned af[4][4];
#pragma unroll
            for (int mi = 0; mi < 4; mi++)
                ldm4(af[mi], tA + SW128((wm * 64 + mi * 16 + lr) * 128 + cs2));
            unsigned b0[2][4];
#pragma unroll
            for (int nb = 0; nb < 2; nb++)
                ldm4(b0[nb], tW0 + SW128((wn * 32 + nb * 16 + lr) * 128 + cs2));
            unsigned b1[2][4];
            if (TERMS == 2) {
#pragma unroll
                for (int nb = 0; nb < 2; nb++)
                    ldm4(b1[nb], tW1 + SW128((wn * 32 + nb * 16 + lr) * 128 + cs2));
            }
#pragma unroll
            for (int mi = 0; mi < 4; mi++) {
#pragma unroll
                for (int nj = 0; nj < 4; nj++) {
                    const int nb = nj >> 1, sl = nj & 1;
                    mma16816(acc[mi][nj], af[mi], b0[nb][sl], b0[nb][2 + sl]);
                    if (TERMS == 2)
                        mma16816(acc[mi][nj], af[mi], b1[nb][sl], b1[nb][2 + sl]);
                }
            }
        }
    }

    const int g = lane >> 2, tg = lane & 3;
#pragma unroll
    for (int mi = 0; mi < 4; mi++) {
#pragma unroll
        for (int nj = 0; nj < 4; nj++) {
            int m0 = bm + wm * 64 + mi * 16 + g;
            int n0 = bn + wn * 32 + nj * 8 + tg * 2;
            float2 bs = *(const float2*)(bias + n0);
            float v0 = acc[mi][nj][0] + bs.x;
            float v1 = acc[mi][nj][1] + bs.y;
            float v2 = acc[mi][nj][2] + bs.x;
            float v3 = acc[mi][nj][3] + bs.y;
            if (MISHE) {
                float2 r0 = *(const float2*)(resid + (size_t)m0 * D_ + n0);
                float2 r1 = *(const float2*)(resid + (size_t)(m0 + 8) * D_ + n0);
                v0 = r0.x + mishf(v0);
                v1 = r0.y + mishf(v1);
                v2 = r1.x + mishf(v2);
                v3 = r1.y + mishf(v3);
            }
            if (HOUT) {
                __half h0 = __float2half_rn(v0), h1 = __float2half_rn(v1);
                __half h2 = __float2half_rn(v2), h3 = __float2half_rn(v3);
                *(unsigned*)(Oh + (size_t)m0 * D_ + n0)       = packh2(h0, h1);
                *(unsigned*)(Oh + (size_t)(m0 + 8) * D_ + n0) = packh2(h2, h3);
                *(unsigned*)(Ol + (size_t)m0 * D_ + n0) =
                    packh2(__float2half_rn(v0 - __half2float(h0)),
                           __float2half_rn(v1 - __half2float(h1)));
                *(unsigned*)(Ol + (size_t)(m0 + 8) * D_ + n0) =
                    packh2(__float2half_rn(v2 - __half2float(h2)),
                           __float2half_rn(v3 - __half2float(h3)));
            } else {
                *(float2*)(C + (size_t)m0 * D_ + n0)       = make_float2(v0, v1);
                *(float2*)(C + (size_t)(m0 + 8) * D_ + n0) = make_float2(v2, v3);
            }
        }
    }
}

// ---------------- LayerNorm + LIF + bit-pack ----------------
__global__ __launch_bounds__(256)
void ln_lif_pack(const float* __restrict__ X,
                 const float* __restrict__ gamma, const float* __restrict__ beta,
                 unsigned* __restrict__ bits)
{
    const int row  = blockIdx.x;
    const int t    = threadIdx.x;
    const int lane = t & 31;
    const int wid  = t >> 5;

    const float* xr = X + (size_t)row * D_;

    float x[4];
    float s = 0.f, sq = 0.f;
#pragma unroll
    for (int i = 0; i < 4; i++) {
        x[i] = xr[i * 256 + t];
        s  += x[i];
        sq += x[i] * x[i];
    }
#pragma unroll
    for (int off = 16; off > 0; off >>= 1) {
        s  += __shfl_xor_sync(0xffffffffu, s,  off);
        sq += __shfl_xor_sync(0xffffffffu, sq, off);
    }
    __shared__ float ss[8], sqq[8];
    __shared__ float s_mu, s_rs;
    if (lane == 0) { ss[wid] = s; sqq[wid] = sq; }
    __syncthreads();
    if (wid == 0) {
        float a = (lane < 8) ? ss[lane]  : 0.f;
        float b = (lane < 8) ? sqq[lane] : 0.f;
#pragma unroll
        for (int off = 4; off > 0; off >>= 1) {
            a += __shfl_xor_sync(0xffffffffu, a, off);
            b += __shfl_xor_sync(0xffffffffu, b, off);
        }
        if (lane == 0) {
            float mu  = a * (1.f / D_);
            float var = b * (1.f / D_) - mu * mu;
            s_mu = mu;
            s_rs = rsqrtf(var + EPS_);
        }
    }
    __syncthreads();
    const float mu = s_mu, rs = s_rs;

#pragma unroll
    for (int i = 0; i < 4; i++) {
        int d = i * 256 + t;
        float y = (x[i] - mu) * rs * gamma[d] + beta[d];
        unsigned word = __ballot_sync(0xffffffffu, y >= 2.0f);
        if (lane == 0) bits[(size_t)row * 32 + i * 8 + wid] = word;
    }
}

// ---------------- HMMA flash attention (bit mask + exp LUT) ----------------
#define AT_PH   0                       // half  [128][40]      10240
#define AT_PL   10240                   // half  [128][40]      10240
#define AT_VH   20480                   // half  [2][32][72]     9216
#define AT_VL   29696                   // half  [2][32][72]     9216
#define AT_KB   38912                   // unsigned [1024][2]    8192
#define AT_SUM  47104                   // float [128]            512
#define AT_LUT  47616                   // float [65]             260
#define AT_SMEM (47616 + 512 + 1024)

__global__ __launch_bounds__(128, 3)
void attn_kernel(const unsigned* __restrict__ qbits, const unsigned* __restrict__ kbits,
                 const __half* __restrict__ Vh, const __half* __restrict__ Vl,
                 const unsigned* __restrict__ mbits,
                 float* __restrict__ out, __half* __restrict__ outh)
{
    extern __shared__ char raw[];
    char* sb = (char*)(((uintptr_t)raw + 1023) & ~(uintptr_t)1023);
    __half*   sPh  = (__half*)(sb + AT_PH);    // stride 40
    __half*   sPl  = (__half*)(sb + AT_PL);
    __half*   sVh  = (__half*)(sb + AT_VH);    // [buf][32][72]
    __half*   sVl  = (__half*)(sb + AT_VL);
    unsigned* sKb  = (unsigned*)(sb + AT_KB);  // [1024][2]
    float*    sSum = (float*)(sb + AT_SUM);
    float*    sLut = (float*)(sb + AT_LUT);

    const int qblk = blockIdx.x;
    const int h    = blockIdx.y;
    const int b    = blockIdx.z;
    const int t    = threadIdx.x;
    const int lane = t & 31;
    const int wid  = t >> 5;

    const unsigned q0 = qbits[((size_t)(b * S_ + qblk * 128 + t)) * 32 + h * 2 + 0];
    const unsigned q1 = qbits[((size_t)(b * S_ + qblk * 128 + t)) * 32 + h * 2 + 1];

    float acc[2][8][4];
#pragma unroll
    for (int i = 0; i < 2; i++)
#pragma unroll
        for (int j = 0; j < 8; j++)
#pragma unroll
            for (int r = 0; r < 4; r++) acc[i][j][r] = 0.f;
    float ssum = 0.f;

    auto loadV = [&](int c) {
        __half* dvh = sVh + (c & 1) * 32 * 72;
        __half* dvl = sVl + (c & 1) * 32 * 72;
        const size_t gb = ((size_t)(b * S_ + c * 32)) * D_ + h * HD_;
#pragma unroll
        for (int i = 0; i < 2; i++) {
            int id = i * 128 + t;
            int r  = id >> 3, ch = id & 7;
            cpa16(smem_u32(dvh + r * 72 + ch * 8), Vh + gb + (size_t)r * D_ + ch * 8);
            cpa16(smem_u32(dvl + r * 72 + ch * 8), Vl + gb + (size_t)r * D_ + ch * 8);
        }
    };

    // preload K bits (full column), LUT
#pragma unroll
    for (int i = 0; i < 8; i++) {
        int j = i * 128 + t;
        *(uint2*)&sKb[j * 2] = *(const uint2*)&kbits[((size_t)(b * S_ + j)) * 32 + h * 2];
    }
    if (t < 65) sLut[t] = __expf((float)t * 0.125f);

    loadV(0);
    asm volatile("cp.async.commit_group;" ::: "memory");

    const unsigned* mrow = mbits + b * 32 * S_ + qblk * 128 + t;
    unsigned mw = mrow[0];
    __syncthreads();   // sKb, sLut visible

    for (int c = 0; c < 32; c++) {
        const int k0 = c * 32;

        if (c + 1 < 32) loadV(c + 1);
        asm volatile("cp.async.commit_group;" ::: "memory");
        unsigned mw_next = (c + 1 < 32) ? mrow[(c + 1) * S_] : 0u;

        // e-compute: thread t owns q-row t
        {
            __half* ph = sPh + t * 40;
            __half* pl = sPl + t * 40;
#pragma unroll
            for (int j = 0; j < 32; j += 2) {
                int s0 = __popc(q0 & sKb[(k0 + j) * 2])     + __popc(q1 & sKb[(k0 + j) * 2 + 1]);
                int s1 = __popc(q0 & sKb[(k0 + j + 1) * 2]) + __popc(q1 & sKb[(k0 + j + 1) * 2 + 1]);
                float e0 = sLut[s0 * ((mw >> j) & 1)];
                float e1 = sLut[s1 * ((mw >> (j + 1)) & 1)];
                ssum += e0 + e1;
                __half h0 = __float2half_rn(e0), h1 = __float2half_rn(e1);
                *(unsigned*)(ph + j) = packh2(h0, h1);
                *(unsigned*)(pl + j) = packh2(__float2half_rn(e0 - __half2float(h0)),
                                              __float2half_rn(e1 - __half2float(h1)));
            }
        }
        mw = mw_next;
        __syncthreads();   // sP visible
        asm volatile("cp.async.wait_group 1;" ::: "memory");  // V(c) ready

        // MMA: P[128x32] @ V[32x64], 3 terms
        const __half* vhb = sVh + (c & 1) * 32 * 72;
        const __half* vlb = sVl + (c & 1) * 32 * 72;
        const int lr  = lane & 15;
        const int lc8 = (lane >> 4) * 8;
        const int l8  = lane & 7;
        const int ks8 = ((lane >> 3) & 1) * 8;
        const int ns8 = (lane >> 4) * 8;
#pragma unroll
        for (int kk = 0; kk < 2; kk++) {
            unsigned ah[2][4], al[2][4];
#pragma unroll
            for (int mi = 0; mi < 2; mi++) {
                const int rofs = (wid * 32 + mi * 16 + lr) * 40 + kk * 16 + lc8;
                ldm4(ah[mi], sPh + rofs);
                ldm4(al[mi], sPl + rofs);
            }
            unsigned vh[4][4], vl[4][4];
#pragma unroll
            for (int nb = 0; nb < 4; nb++) {
                const int vofs = (kk * 16 + ks8 + l8) * 72 + nb * 16 + ns8;
                ldm4t(vh[nb], vhb + vofs);
                ldm4t(vl[nb], vlb + vofs);
            }
#pragma unroll
            for (int mi = 0; mi < 2; mi++) {
#pragma unroll
                for (int nj = 0; nj < 8; nj++) {
                    const int nb = nj >> 1, half = nj & 1;
                    mma16816(acc[mi][nj], ah[mi], vh[nb][half * 2], vh[nb][half * 2 + 1]);
                    mma16816(acc[mi][nj], al[mi], vh[nb][half * 2], vh[nb][half * 2 + 1]);
                    mma16816(acc[mi][nj], ah[mi], vl[nb][half * 2], vl[nb][half * 2 + 1]);
                }
            }
        }
        __syncthreads();   // MMA done; sP reusable next iter
    }

    sSum[t] = ssum;
    __syncthreads();

    const int g = lane >> 2, tg = lane & 3;
#pragma unroll
    for (int mi = 0; mi < 2; mi++) {
        const int qr0 = wid * 32 + mi * 16 + g;
        const float inv0 = 1.f / sSum[qr0];
        const float inv1 = 1.f / sSum[qr0 + 8];
        const size_t base0 = ((size_t)(b * S_ + qblk * 128 + qr0)) * D_ + h * HD_;
#pragma unroll
        for (int nj = 0; nj < 8; nj++) {
            const int n = nj * 8 + tg * 2;
            float v0 = acc[mi][nj][0] * inv0;
            float v1 = acc[mi][nj][1] * inv0;
            float v2 = acc[mi][nj][2] * inv1;
            float v3 = acc[mi][nj][3] * inv1;
            *(float2*)(out + base0 + n)           = make_float2(v0, v1);
            *(float2*)(out + base0 + 8 * D_ + n)  = make_float2(v2, v3);
            *(unsigned*)(outh + base0 + n)          = packh2(__float2half_rn(v0), __float2half_rn(v1));
            *(unsigned*)(outh + base0 + 8 * D_ + n) = packh2(__float2half_rn(v2), __float2half_rn(v3));
        }
    }
}

// ---------------- launch ----------------
extern "C" void kernel_launch(void* const* d_in, const int* in_sizes, int n_in,
                              void* d_out, int out_size)
{
    const float* Q   = (const float*)d_in[0];
    const float* K_  = (const float*)d_in[1];
    const float* adj = (const float*)d_in[2];
    const float* Wq  = (const float*)d_in[3];
    const float* bq  = (const float*)d_in[4];
    const float* Wk  = (const float*)d_in[5];
    const float* bk  = (const float*)d_in[6];
    const float* Wv  = (const float*)d_in[7];
    const float* bv  = (const float*)d_in[8];
    const float* Wo  = (const float*)d_in[9];
    const float* bo  = (const float*)d_in[10];
    const float* gq  = (const float*)d_in[11];
    const float* beq = (const float*)d_in[12];
    const float* gk  = (const float*)d_in[13];
    const float* bek = (const float*)d_in[14];
    float* out = (float*)d_out;

    float *Xq, *Xk, *At;
    __half *Qb, *Kb, *Ath, *Vh, *Vl, *Wqh, *Wql, *Wkh, *Wkl, *Wv1, *Wo1;
    unsigned *qb, *kb, *mb;
    cudaGetSymbolAddress((void**)&Xq,  g_Xq);
    cudaGetSymbolAddress((void**)&Xk,  g_Xk);
    cudaGetSymbolAddress((void**)&At,  g_At);
    cudaGetSymbolAddress((void**)&Qb,  g_Qb);
    cudaGetSymbolAddress((void**)&Kb,  g_Kb);
    cudaGetSymbolAddress((void**)&Ath, g_Ath);
    cudaGetSymbolAddress((void**)&Vh,  g_Vh);
    cudaGetSymbolAddress((void**)&Vl,  g_Vl);
    cudaGetSymbolAddress((void**)&Wqh, g_Wqh);
    cudaGetSymbolAddress((void**)&Wql, g_Wql);
    cudaGetSymbolAddress((void**)&Wkh, g_Wkh);
    cudaGetSymbolAddress((void**)&Wkl, g_Wkl);
    cudaGetSymbolAddress((void**)&Wv1, g_Wv1);
    cudaGetSymbolAddress((void**)&Wo1, g_Wo1);
    cudaGetSymbolAddress((void**)&qb,  g_qb);
    cudaGetSymbolAddress((void**)&kb,  g_kb);
    cudaGetSymbolAddress((void**)&mb,  g_mb);

    const int smem2 = 4 * 3 * TILEB + 1024;
    const int smem1 = 3 * 2 * TILEB + 1024;
    cudaFuncSetAttribute((const void*)hgemm<2, false, false, 4>,
                         cudaFuncAttributeMaxDynamicSharedMemorySize, smem2);
    cudaFuncSetAttribute((const void*)hgemm<1, false, true, 3>,
                         cudaFuncAttributeMaxDynamicSharedMemorySize, smem1);
    cudaFuncSetAttribute((const void*)hgemm<1, true, false, 3>,
                         cudaFuncAttributeMaxDynamicSharedMemorySize, smem1);
    cudaFuncSetAttribute((const void*)attn_kernel,
                         cudaFuncAttributeMaxDynamicSharedMemorySize, AT_SMEM);

    const int WELEM = D_ * D_;
    prep_w2<<<WELEM / 4 / 256, 256>>>(Wq, Wqh, Wql);
    prep_w2<<<WELEM / 4 / 256, 256>>>(Wk, Wkh, Wkl);
    prep_w1<<<WELEM / 4 / 256, 256>>>(Wv, Wv1);
    prep_w1<<<WELEM / 4 / 256, 256>>>(Wo, Wo1);
    prep_bin<<<ROWS * D_ / 4 / 256, 256>>>(Q,  Qb);
    prep_bin<<<ROWS * D_ / 4 / 256, 256>>>(K_, Kb);
    prep_mask<<<B_ * 32 * S_ / 256, 256>>>(adj, mb);

    dim3 gg(D_ / 128, ROWS / 128);

    hgemm<2, false, false, 4><<<gg, 256, smem2>>>(Qb, Wqh, Wql, bq, nullptr, Xq, nullptr, nullptr);
    hgemm<2, false, false, 4><<<gg, 256, smem2>>>(Kb, Wkh, Wkl, bk, nullptr, Xk, nullptr, nullptr);
    hgemm<1, false, true, 3><<<gg, 256, smem1>>>(Kb, Wv1, nullptr, bv, nullptr, nullptr, Vh, Vl);

    ln_lif_pack<<<ROWS, 256>>>(Xq, gq, beq, qb);
    ln_lif_pack<<<ROWS, 256>>>(Xk, gk, bek, kb);

    attn_kernel<<<dim3(8, H_, B_), 128, AT_SMEM>>>(qb, kb, Vh, Vl, mb, At, Ath);

    hgemm<1, true, false, 3><<<gg, 256, smem1>>>(Ath, Wo1, nullptr, bo, At, out, nullptr, nullptr);
}